// round 4
// baseline (speedup 1.0000x reference)
#include <cuda_runtime.h>
#include <math.h>

// ---------------- problem constants ----------------
#define Bsz   8
#define Tsz   1024
#define Dsz   1024
#define Nsz   256
#define Lsz   768
#define Hsz   16
#define HDsz  64
#define TEsz  2048
#define D2sz  2048
#define EPSv  1e-5f

// ---------------- scratch (device globals; allocation-free) ----------------
__device__ float g_xn  [Bsz * Tsz * Dsz];           // LN(x)
__device__ float g_xfn [Bsz * Nsz * Lsz];           // LN(xf)
__device__ float g_q   [Bsz * Tsz * Dsz];
__device__ float g_k   [Bsz * Nsz * Dsz];
__device__ float g_v   [Bsz * Nsz * Dsz];
__device__ float g_s   [(size_t)Bsz * Hsz * Tsz * Nsz];   // scores (b,h,t,n) 128MB
__device__ float g_y   [Bsz * Tsz * Dsz];
__device__ float g_semb[Bsz * TEsz];
__device__ float g_emb [Bsz * D2sz];                // emb_out (scale|shift)

// ---------------- LayerNorm over last dim ----------------
__global__ void ln_kernel(const float* __restrict__ in,
                          const float* __restrict__ g,
                          const float* __restrict__ b,
                          float* __restrict__ out, int C) {
    int row = blockIdx.x;
    const float* ip = in + (size_t)row * C;
    float* op = out + (size_t)row * C;
    int tid = threadIdx.x;
    float v[4];
    float s = 0.f, ss = 0.f;
#pragma unroll
    for (int i = 0; i < 4; i++) {
        int c = tid + i * 256;
        float x = (c < C) ? ip[c] : 0.f;
        v[i] = x; s += x; ss += x * x;
    }
    __shared__ float rs[256], rq[256];
    rs[tid] = s; rq[tid] = ss;
    __syncthreads();
    for (int off = 128; off > 0; off >>= 1) {
        if (tid < off) { rs[tid] += rs[tid + off]; rq[tid] += rq[tid + off]; }
        __syncthreads();
    }
    float mean = rs[0] / (float)C;
    float var  = rq[0] / (float)C - mean * mean;
    float inv  = rsqrtf(var + EPSv);
#pragma unroll
    for (int i = 0; i < 4; i++) {
        int c = tid + i * 256;
        if (c < C) op[c] = (v[i] - mean) * inv * g[c] + b[c];
    }
}

// ---------------- LN + (1+scale)/shift modulate + SiLU (StylizationBlock front) ----------------
__global__ void styl_kernel(const float* __restrict__ y,
                            const float* __restrict__ g,
                            const float* __restrict__ b,
                            const float* __restrict__ embout,
                            float* __restrict__ out) {
    int row = blockIdx.x;                 // 0..B*T-1
    int batch = row / Tsz;
    const float* ip = y + (size_t)row * Dsz;
    float* op = out + (size_t)row * Dsz;
    const float* sc = embout + (size_t)batch * D2sz;          // scale
    const float* sh = embout + (size_t)batch * D2sz + Dsz;    // shift
    int tid = threadIdx.x;
    float v[4];
    float s = 0.f, ss = 0.f;
#pragma unroll
    for (int i = 0; i < 4; i++) {
        int c = tid + i * 256;
        float x = ip[c];
        v[i] = x; s += x; ss += x * x;
    }
    __shared__ float rs[256], rq[256];
    rs[tid] = s; rq[tid] = ss;
    __syncthreads();
    for (int off = 128; off > 0; off >>= 1) {
        if (tid < off) { rs[tid] += rs[tid + off]; rq[tid] += rq[tid + off]; }
        __syncthreads();
    }
    float mean = rs[0] / (float)Dsz;
    float var  = rq[0] / (float)Dsz - mean * mean;
    float inv  = rsqrtf(var + EPSv);
#pragma unroll
    for (int i = 0; i < 4; i++) {
        int c = tid + i * 256;
        float h = (v[i] - mean) * inv * g[c] + b[c];
        h = h * (1.f + sc[c]) + sh[c];
        op[c] = h / (1.f + expf(-h));     // silu
    }
}

// ---------------- elementwise silu ----------------
__global__ void silu_kernel(const float* __restrict__ in, float* __restrict__ out, int n) {
    int i = blockIdx.x * blockDim.x + threadIdx.x;
    if (i < n) { float x = in[i]; out[i] = x / (1.f + expf(-x)); }
}

// ---------------- small emb GEMM: out(8,2048) = se(8,2048) @ W(2048,2048) + bias ----------------
__global__ void embgemm_kernel(const float* __restrict__ se,
                               const float* __restrict__ W,
                               const float* __restrict__ bias,
                               float* __restrict__ out) {
    int tid  = threadIdx.x;
    int lane = tid & 31;
    int ks   = tid >> 5;                       // 0..7 k-slice
    int col  = blockIdx.x * 32 + lane;         // 64 blocks * 32 cols
    float acc[8] = {0,0,0,0,0,0,0,0};
    int k0 = ks * 256;
    for (int kk = k0; kk < k0 + 256; kk++) {
        float w = W[(size_t)kk * D2sz + col];
#pragma unroll
        for (int r = 0; r < 8; r++) acc[r] = fmaf(se[r * TEsz + kk], w, acc[r]);
    }
    __shared__ float sp[8][8][32];
#pragma unroll
    for (int r = 0; r < 8; r++) sp[ks][r][lane] = acc[r];
    __syncthreads();
    int r = tid >> 5;
    float sum = 0.f;
#pragma unroll
    for (int s2 = 0; s2 < 8; s2++) sum += sp[s2][r][lane];
    out[(size_t)r * D2sz + col] = sum + bias[col];
}

// ---------------- softmax over last dim (rows of 256), scale 1/sqrt(64) folded ----------------
__global__ void softmax_kernel(float* __restrict__ S) {
    int row  = blockIdx.x * 8 + (threadIdx.x >> 5);
    int lane = threadIdx.x & 31;
    float* p = S + (size_t)row * Nsz + lane * 8;
    float4 a = *reinterpret_cast<float4*>(p);
    float4 b = *reinterpret_cast<float4*>(p + 4);
    const float sc = 0.125f;
    float v[8] = {a.x*sc, a.y*sc, a.z*sc, a.w*sc, b.x*sc, b.y*sc, b.z*sc, b.w*sc};
    float m = v[0];
#pragma unroll
    for (int i = 1; i < 8; i++) m = fmaxf(m, v[i]);
#pragma unroll
    for (int off = 16; off > 0; off >>= 1)
        m = fmaxf(m, __shfl_xor_sync(0xffffffffu, m, off));
    float sum = 0.f;
#pragma unroll
    for (int i = 0; i < 8; i++) { v[i] = __expf(v[i] - m); sum += v[i]; }
#pragma unroll
    for (int off = 16; off > 0; off >>= 1)
        sum += __shfl_xor_sync(0xffffffffu, sum, off);
    float inv = 1.f / sum;
    a.x = v[0]*inv; a.y = v[1]*inv; a.z = v[2]*inv; a.w = v[3]*inv;
    b.x = v[4]*inv; b.y = v[5]*inv; b.z = v[6]*inv; b.w = v[7]*inv;
    *reinterpret_cast<float4*>(p)     = a;
    *reinterpret_cast<float4*>(p + 4) = b;
}

// ---------------- generic strided (batched) tiled SGEMM ----------------
// C[m,n] = sum_k A[m,k] * (TRB ? Bm[n,k] : Bm[k,n])  (+bias[n]) (+addsrc[m,n])
// batch z decomposed as zb = z/Hdiv, zh = z%Hdiv with two-level strides.
template<int BM, int BN, int BK, int TM, int TN, bool TRB, bool HAS_BIAS, bool HAS_ADD>
__global__ void gemm_kernel(int M, int N, int K,
                            const float* __restrict__ A, int lda, long long sAb, long long sAh,
                            const float* __restrict__ Bm, int ldb, long long sBb, long long sBh,
                            float* __restrict__ C, int ldc, long long sCb, long long sCh,
                            const float* __restrict__ bias,
                            const float* __restrict__ addsrc, int ldadd,
                            int Hdiv) {
    int z  = blockIdx.z;
    int zb = z / Hdiv, zh = z % Hdiv;
    A  += (size_t)zb * sAb + (size_t)zh * sAh;
    Bm += (size_t)zb * sBb + (size_t)zh * sBh;
    C  += (size_t)zb * sCb + (size_t)zh * sCh;
    if (HAS_ADD) addsrc += (size_t)zb * sCb + (size_t)zh * sCh;

    const int bm = blockIdx.y * BM;
    const int bn = blockIdx.x * BN;

    __shared__ float As[BK][BM];
    __shared__ float Bs[BK][BN];

    const int tid   = threadIdx.x;         // 256
    const int tcols = BN / TN;
    const int tr    = tid / tcols;
    const int tc    = tid % tcols;

    float acc[TM][TN];
#pragma unroll
    for (int i = 0; i < TM; i++)
#pragma unroll
        for (int j = 0; j < TN; j++) acc[i][j] = 0.f;
    float regM[TM], regN[TN];

    for (int k0 = 0; k0 < K; k0 += BK) {
        // A tile: BM x BK, float4 along k
        constexpr int AF4 = (BM * BK / 4) / 256;
#pragma unroll
        for (int i = 0; i < AF4; i++) {
            int idx = tid + i * 256;
            int row = idx / (BK / 4);
            int kv  = idx % (BK / 4);
            float4 t = *reinterpret_cast<const float4*>(&A[(size_t)(bm + row) * lda + k0 + kv * 4]);
            As[kv*4+0][row] = t.x; As[kv*4+1][row] = t.y;
            As[kv*4+2][row] = t.z; As[kv*4+3][row] = t.w;
        }
        if (!TRB) {
            constexpr int BF4 = (BK * BN / 4) / 256;
#pragma unroll
            for (int i = 0; i < BF4; i++) {
                int idx = tid + i * 256;
                int kk = idx / (BN / 4);
                int nv = idx % (BN / 4);
                float4 t = *reinterpret_cast<const float4*>(&Bm[(size_t)(k0 + kk) * ldb + bn + nv * 4]);
                *reinterpret_cast<float4*>(&Bs[kk][nv * 4]) = t;
            }
        } else {
            constexpr int BF4 = (BN * BK / 4) / 256;
#pragma unroll
            for (int i = 0; i < BF4; i++) {
                int idx = tid + i * 256;
                int row = idx / (BK / 4);      // n
                int kv  = idx % (BK / 4);
                float4 t = *reinterpret_cast<const float4*>(&Bm[(size_t)(bn + row) * ldb + k0 + kv * 4]);
                Bs[kv*4+0][row] = t.x; Bs[kv*4+1][row] = t.y;
                Bs[kv*4+2][row] = t.z; Bs[kv*4+3][row] = t.w;
            }
        }
        __syncthreads();
#pragma unroll
        for (int kk = 0; kk < BK; kk++) {
#pragma unroll
            for (int i = 0; i < TM; i++) regM[i] = As[kk][tr * TM + i];
#pragma unroll
            for (int j = 0; j < TN; j++) regN[j] = Bs[kk][tc * TN + j];
#pragma unroll
            for (int i = 0; i < TM; i++)
#pragma unroll
                for (int j = 0; j < TN; j++)
                    acc[i][j] = fmaf(regM[i], regN[j], acc[i][j]);
        }
        __syncthreads();
    }

#pragma unroll
    for (int i = 0; i < TM; i++) {
        int m = bm + tr * TM + i;
#pragma unroll
        for (int j = 0; j < TN; j += 4) {
            int n = bn + tc * TN + j;
            float4 r;
            r.x = acc[i][j]; r.y = acc[i][j+1]; r.z = acc[i][j+2]; r.w = acc[i][j+3];
            if (HAS_BIAS) {
                r.x += bias[n];   r.y += bias[n+1];
                r.z += bias[n+2]; r.w += bias[n+3];
            }
            if (HAS_ADD) {
                float4 a4 = *reinterpret_cast<const float4*>(&addsrc[(size_t)m * ldadd + n]);
                r.x += a4.x; r.y += a4.y; r.z += a4.z; r.w += a4.w;
            }
            *reinterpret_cast<float4*>(&C[(size_t)m * ldc + n]) = r;
        }
    }
}

// ---------------- launch ----------------
extern "C" void kernel_launch(void* const* d_in, const int* in_sizes, int n_in,
                              void* d_out, int out_size) {
    const float* x    = (const float*)d_in[0];
    const float* xf   = (const float*)d_in[1];
    const float* emb  = (const float*)d_in[2];
    const float* ln_g = (const float*)d_in[3];
    const float* ln_b = (const float*)d_in[4];
    const float* cln_g= (const float*)d_in[5];
    const float* cln_b= (const float*)d_in[6];
    const float* Wq   = (const float*)d_in[7];
    const float* bq   = (const float*)d_in[8];
    const float* Wk   = (const float*)d_in[9];
    const float* bk   = (const float*)d_in[10];
    const float* Wv   = (const float*)d_in[11];
    const float* bv   = (const float*)d_in[12];
    const float* sln_g= (const float*)d_in[13];
    const float* sln_b= (const float*)d_in[14];
    const float* Wemb = (const float*)d_in[15];
    const float* bemb = (const float*)d_in[16];
    const float* Wout = (const float*)d_in[17];
    const float* bout = (const float*)d_in[18];
    float* out = (float*)d_out;

    float *xn, *xfn, *q, *k, *v, *s, *y, *semb, *embo;
    cudaGetSymbolAddress((void**)&xn,   g_xn);
    cudaGetSymbolAddress((void**)&xfn,  g_xfn);
    cudaGetSymbolAddress((void**)&q,    g_q);
    cudaGetSymbolAddress((void**)&k,    g_k);
    cudaGetSymbolAddress((void**)&v,    g_v);
    cudaGetSymbolAddress((void**)&s,    g_s);
    cudaGetSymbolAddress((void**)&y,    g_y);
    cudaGetSymbolAddress((void**)&semb, g_semb);
    cudaGetSymbolAddress((void**)&embo, g_emb);

    // 1. LayerNorms
    ln_kernel<<<Bsz * Tsz, 256>>>(x,  ln_g,  ln_b,  xn,  Dsz);
    ln_kernel<<<Bsz * Nsz, 256>>>(xf, cln_g, cln_b, xfn, Lsz);

    // 2. emb path: silu then small GEMM -> (scale|shift)
    silu_kernel<<<(Bsz * TEsz + 255) / 256, 256>>>(emb, semb, Bsz * TEsz);
    embgemm_kernel<<<64, 256>>>(semb, Wemb, bemb, embo);

    // 3. projections
    gemm_kernel<128,128,16,8,8,false,true,false><<<dim3(Dsz/128, (Bsz*Tsz)/128, 1), 256>>>(
        Bsz*Tsz, Dsz, Dsz, xn, Dsz, 0, 0, Wq, Dsz, 0, 0, q, Dsz, 0, 0, bq, nullptr, 0, 1);
    gemm_kernel<128,128,16,8,8,false,true,false><<<dim3(Dsz/128, (Bsz*Nsz)/128, 1), 256>>>(
        Bsz*Nsz, Dsz, Lsz, xfn, Lsz, 0, 0, Wk, Dsz, 0, 0, k, Dsz, 0, 0, bk, nullptr, 0, 1);
    gemm_kernel<128,128,16,8,8,false,true,false><<<dim3(Dsz/128, (Bsz*Nsz)/128, 1), 256>>>(
        Bsz*Nsz, Dsz, Lsz, xfn, Lsz, 0, 0, Wv, Dsz, 0, 0, v, Dsz, 0, 0, bv, nullptr, 0, 1);

    // 4. scores: per (b,h): S(T,N) = q_bh(T,hd) @ k_bh(N,hd)^T, S layout (b,h,t,n)
    {
        long long sAb = (long long)Tsz * Dsz, sAh = HDsz;
        long long sBb = (long long)Nsz * Dsz, sBh = HDsz;
        long long sCb = (long long)Hsz * Tsz * Nsz, sCh = (long long)Tsz * Nsz;
        gemm_kernel<128,128,16,8,8,true,false,false><<<dim3(Nsz/128, Tsz/128, Bsz*Hsz), 256>>>(
            Tsz, Nsz, HDsz, q, Dsz, sAb, sAh, k, Dsz, sBb, sBh,
            s, Nsz, sCb, sCh, nullptr, nullptr, 0, Hsz);
    }

    // 5. softmax over N (scale 1/8 folded in)
    softmax_kernel<<<(Bsz * Hsz * Tsz) / 8, 256>>>(s);

    // 6. y: per (b,h): y_bh(T,hd) = S(T,N) @ v_bh(N,hd), written into (B,T,D)
    {
        long long sAb = (long long)Hsz * Tsz * Nsz, sAh = (long long)Tsz * Nsz;
        long long sBb = (long long)Nsz * Dsz, sBh = HDsz;
        long long sCb = (long long)Tsz * Dsz, sCh = HDsz;
        gemm_kernel<128,64,16,8,4,false,false,false><<<dim3(HDsz/64, Tsz/128, Bsz*Hsz), 256>>>(
            Tsz, HDsz, Nsz, s, Nsz, sAb, sAh, v, Dsz, sBb, sBh,
            y, Dsz, sCb, sCh, nullptr, nullptr, 0, Hsz);
    }

    // 7. stylization front: hbuf = silu(LN(y)*(1+scale)+shift)  (reuse g_xn)
    styl_kernel<<<Bsz * Tsz, 256>>>(y, sln_g, sln_b, embo, xn);

    // 8. out = x + hbuf @ Wout + bout
    gemm_kernel<128,128,16,8,8,false,true,true><<<dim3(Dsz/128, (Bsz*Tsz)/128, 1), 256>>>(
        Bsz*Tsz, Dsz, Dsz, xn, Dsz, 0, 0, Wout, Dsz, 0, 0,
        out, Dsz, 0, 0, bout, x, Dsz, 1);
}

// round 5
// speedup vs baseline: 3.5793x; 3.5793x over previous
#include <cuda_runtime.h>
#include <cuda_bf16.h>
#include <math.h>
#include <stdint.h>
#include <string.h>

// ---------------- problem constants ----------------
#define Bsz   8
#define Tsz   1024
#define Dsz   1024
#define Nsz   256
#define Lsz   768
#define Hsz   16
#define HDsz  64
#define TEsz  2048
#define D2sz  2048
#define EPSv  1e-5f

// ---------------- scratch (device globals; allocation-free) ----------------
__device__ __align__(256) __nv_bfloat16 g_xn_bf [Bsz * Tsz * Dsz];
__device__ __align__(256) __nv_bfloat16 g_xfn_bf[Bsz * Nsz * Lsz];
__device__ __align__(256) __nv_bfloat16 g_q_bf  [Bsz * Tsz * Dsz];
__device__ __align__(256) __nv_bfloat16 g_k_bf  [Bsz * Nsz * Dsz];
__device__ __align__(256) __nv_bfloat16 g_v_bf  [Bsz * Nsz * Dsz];
__device__ __align__(256) __nv_bfloat16 g_s_bf  [(size_t)Bsz * Hsz * Tsz * Nsz]; // 64MB
__device__ __align__(256) float         g_y     [Bsz * Tsz * Dsz];
__device__ __align__(256) __nv_bfloat16 g_h_bf  [Bsz * Tsz * Dsz];
__device__ __align__(256) __nv_bfloat16 g_wqt   [Dsz * Dsz];
__device__ __align__(256) __nv_bfloat16 g_wkt   [Dsz * Lsz];
__device__ __align__(256) __nv_bfloat16 g_wvt   [Dsz * Lsz];
__device__ __align__(256) __nv_bfloat16 g_woutt [Dsz * Dsz];
__device__ __align__(256) float         g_semb  [Bsz * TEsz];
__device__ __align__(256) float         g_embo  [Bsz * D2sz];
__device__ __align__(256) float         g_embp  [8 * Bsz * D2sz];   // split-K partials

// ---------------- LayerNorm over last dim -> bf16 ----------------
__global__ void ln_bf16_kernel(const float* __restrict__ in,
                               const float* __restrict__ g,
                               const float* __restrict__ b,
                               __nv_bfloat16* __restrict__ out, int C) {
    int row = blockIdx.x;
    const float* ip = in + (size_t)row * C;
    __nv_bfloat16* op = out + (size_t)row * C;
    int tid = threadIdx.x;
    float v[4];
    float s = 0.f, ss = 0.f;
#pragma unroll
    for (int i = 0; i < 4; i++) {
        int c = tid + i * 256;
        float x = (c < C) ? ip[c] : 0.f;
        v[i] = x; s += x; ss += x * x;
    }
    __shared__ float rs[256], rq[256];
    rs[tid] = s; rq[tid] = ss;
    __syncthreads();
    for (int off = 128; off > 0; off >>= 1) {
        if (tid < off) { rs[tid] += rs[tid + off]; rq[tid] += rq[tid + off]; }
        __syncthreads();
    }
    float mean = rs[0] / (float)C;
    float var  = rq[0] / (float)C - mean * mean;
    float inv  = rsqrtf(var + EPSv);
#pragma unroll
    for (int i = 0; i < 4; i++) {
        int c = tid + i * 256;
        if (c < C) op[c] = __float2bfloat16_rn((v[i] - mean) * inv * g[c] + b[c]);
    }
}

// ---------------- LN + modulate + SiLU -> bf16 (StylizationBlock front) ----------------
__global__ void styl_kernel(const float* __restrict__ y,
                            const float* __restrict__ g,
                            const float* __restrict__ b,
                            const float* __restrict__ embout,
                            __nv_bfloat16* __restrict__ out) {
    int row = blockIdx.x;                 // 0..B*T-1
    int batch = row / Tsz;
    const float* ip = y + (size_t)row * Dsz;
    __nv_bfloat16* op = out + (size_t)row * Dsz;
    const float* sc = embout + (size_t)batch * D2sz;          // scale
    const float* sh = embout + (size_t)batch * D2sz + Dsz;    // shift
    int tid = threadIdx.x;
    float v[4];
    float s = 0.f, ss = 0.f;
#pragma unroll
    for (int i = 0; i < 4; i++) {
        int c = tid + i * 256;
        float x = ip[c];
        v[i] = x; s += x; ss += x * x;
    }
    __shared__ float rs[256], rq[256];
    rs[tid] = s; rq[tid] = ss;
    __syncthreads();
    for (int off = 128; off > 0; off >>= 1) {
        if (tid < off) { rs[tid] += rs[tid + off]; rq[tid] += rq[tid + off]; }
        __syncthreads();
    }
    float mean = rs[0] / (float)Dsz;
    float var  = rq[0] / (float)Dsz - mean * mean;
    float inv  = rsqrtf(var + EPSv);
#pragma unroll
    for (int i = 0; i < 4; i++) {
        int c = tid + i * 256;
        float h = (v[i] - mean) * inv * g[c] + b[c];
        h = h * (1.f + sc[c]) + sh[c];
        op[c] = __float2bfloat16_rn(h / (1.f + expf(-h)));     // silu
    }
}

// ---------------- elementwise silu ----------------
__global__ void silu_kernel(const float* __restrict__ in, float* __restrict__ out, int n) {
    int i = blockIdx.x * blockDim.x + threadIdx.x;
    if (i < n) { float x = in[i]; out[i] = x / (1.f + expf(-x)); }
}

// ---------------- convert + transpose: [R][C] fp32 -> [C][R] bf16 ----------------
__global__ void transconv_kernel(const float* __restrict__ in,
                                 __nv_bfloat16* __restrict__ out, int R, int C) {
    __shared__ float tile[32][33];
    int c0 = blockIdx.x * 32, r0 = blockIdx.y * 32;
    int tx = threadIdx.x, ty = threadIdx.y;    // 32 x 8
#pragma unroll
    for (int i = 0; i < 32; i += 8)
        tile[ty + i][tx] = in[(size_t)(r0 + ty + i) * C + c0 + tx];
    __syncthreads();
#pragma unroll
    for (int i = 0; i < 32; i += 8)
        out[(size_t)(c0 + ty + i) * R + r0 + tx] = __float2bfloat16_rn(tile[tx][ty + i]);
}

// ---------------- emb GEMM split-K stage 1: partial(8k)(8r)(2048c) ----------------
__global__ void embgemm_part(const float* __restrict__ se,
                             const float* __restrict__ W,
                             float* __restrict__ part) {
    int lane = threadIdx.x & 31, ks = threadIdx.x >> 5;
    int col = blockIdx.x * 32 + lane;
    int k0  = blockIdx.y * 256 + ks * 32;
    float acc[8] = {0,0,0,0,0,0,0,0};
#pragma unroll 4
    for (int kk = k0; kk < k0 + 32; kk++) {
        float w = W[(size_t)kk * D2sz + col];
#pragma unroll
        for (int r = 0; r < 8; r++) acc[r] = fmaf(se[r * TEsz + kk], w, acc[r]);
    }
    __shared__ float sp[8][8][32];
#pragma unroll
    for (int r = 0; r < 8; r++) sp[ks][r][lane] = acc[r];
    __syncthreads();
    int r = threadIdx.x >> 5;
    float s = 0.f;
#pragma unroll
    for (int s2 = 0; s2 < 8; s2++) s += sp[s2][r][lane];
    part[((size_t)blockIdx.y * 8 + r) * D2sz + col] = s;
}

__global__ void embgemm_reduce(const float* __restrict__ part,
                               const float* __restrict__ bias,
                               float* __restrict__ out) {
    int i = blockIdx.x * 256 + threadIdx.x;    // 8*2048
    int r = i / D2sz, c = i % D2sz;
    float s = bias[c];
#pragma unroll
    for (int p = 0; p < 8; p++) s += part[((size_t)p * 8 + r) * D2sz + c];
    out[i] = s;
}

// ---------------- softmax over N=256 (bf16 in/out), 1/8 scale folded ----------------
__global__ void softmax_kernel(__nv_bfloat16* __restrict__ S) {
    int row  = blockIdx.x * 8 + (threadIdx.x >> 5);
    int lane = threadIdx.x & 31;
    __nv_bfloat16* p = S + (size_t)row * Nsz + lane * 8;
    uint4 t = *reinterpret_cast<uint4*>(p);
    __nv_bfloat16 vb[8];
    memcpy(vb, &t, 16);
    float v[8];
#pragma unroll
    for (int i = 0; i < 8; i++) v[i] = __bfloat162float(vb[i]) * 0.125f;
    float m = v[0];
#pragma unroll
    for (int i = 1; i < 8; i++) m = fmaxf(m, v[i]);
#pragma unroll
    for (int off = 16; off > 0; off >>= 1)
        m = fmaxf(m, __shfl_xor_sync(0xffffffffu, m, off));
    float sum = 0.f;
#pragma unroll
    for (int i = 0; i < 8; i++) { v[i] = __expf(v[i] - m); sum += v[i]; }
#pragma unroll
    for (int off = 16; off > 0; off >>= 1)
        sum += __shfl_xor_sync(0xffffffffu, sum, off);
    float inv = 1.f / sum;
#pragma unroll
    for (int i = 0; i < 8; i++) vb[i] = __float2bfloat16_rn(v[i] * inv);
    memcpy(&t, vb, 16);
    *reinterpret_cast<uint4*>(p) = t;
}

// ---------------- bf16 tensor-core GEMM (mma.sync m16n8k16, fp32 accum) ----------------
__device__ __forceinline__ void mma16816(float* c, const uint32_t* a, const uint32_t* b) {
    asm volatile(
        "mma.sync.aligned.m16n8k16.row.col.f32.bf16.bf16.f32 "
        "{%0,%1,%2,%3}, {%4,%5,%6,%7}, {%8,%9}, {%0,%1,%2,%3};\n"
        : "+f"(c[0]), "+f"(c[1]), "+f"(c[2]), "+f"(c[3])
        : "r"(a[0]), "r"(a[1]), "r"(a[2]), "r"(a[3]), "r"(b[0]), "r"(b[1]));
}

// C[m,n] = sum_k A[m,k] * (TRB ? B[n,k] : B[k,n])  (+bias[n]) (+addsrc[m,n])
// A,B bf16 (k-contig A; B k-contig if TRB else n-contig). BK=32, LDK pad 40.
// Batch z: zb = z/Hdiv, zh = z%Hdiv.
template<int BM, int BN, int WROWS, int WCOLS, bool TRB, bool HAS_BIAS, bool HAS_ADD, bool OUT_BF16>
__global__ void __launch_bounds__(WROWS * WCOLS * 32, 2)
mma_gemm(int M, int N, int K,
         const __nv_bfloat16* __restrict__ A, int lda, long long sAb, long long sAh,
         const __nv_bfloat16* __restrict__ Bm, int ldb, long long sBb, long long sBh,
         void* __restrict__ Cv, int ldc, long long sCb, long long sCh,
         const float* __restrict__ bias,
         const float* __restrict__ addsrc, int ldadd,
         int Hdiv) {
    constexpr int NT = WROWS * WCOLS * 32;
    constexpr int WM = BM / WROWS, WN = BN / WCOLS;
    constexpr int MFRAG = WM / 16, NFRAG = WN / 8;
    constexpr int LDK = 40;

    int z  = blockIdx.z;
    int zb = z / Hdiv, zh = z % Hdiv;
    A  += (size_t)zb * sAb + (size_t)zh * sAh;
    Bm += (size_t)zb * sBb + (size_t)zh * sBh;
    size_t coff = (size_t)zb * sCb + (size_t)zh * sCh;

    const int bm = blockIdx.y * BM;
    const int bn = blockIdx.x * BN;

    __shared__ __nv_bfloat16 As[BM * LDK];
    __shared__ __nv_bfloat16 Bs[BN * LDK];

    const int tid  = threadIdx.x;
    const int warp = tid >> 5, lane = tid & 31;
    const int wm = (warp / WCOLS) * WM;
    const int wn = (warp % WCOLS) * WN;
    const int rg = lane >> 2;           // 0..7
    const int cg = (lane & 3) * 2;      // 0,2,4,6

    float acc[MFRAG][NFRAG][4];
#pragma unroll
    for (int i = 0; i < MFRAG; i++)
#pragma unroll
        for (int j = 0; j < NFRAG; j++)
#pragma unroll
            for (int r = 0; r < 4; r++) acc[i][j][r] = 0.f;

    for (int k0 = 0; k0 < K; k0 += 32) {
        // ---- A tile: BM x 32, k-contig ----
#pragma unroll
        for (int i = tid; i < BM * 4; i += NT) {
            int row = i >> 2, part = i & 3;
            uint4 t = *reinterpret_cast<const uint4*>(A + (size_t)(bm + row) * lda + k0 + part * 8);
            *reinterpret_cast<uint4*>(&As[row * LDK + part * 8]) = t;
        }
        // ---- B tile -> Bs[n][k] ----
        if (TRB) {
#pragma unroll
            for (int i = tid; i < BN * 4; i += NT) {
                int row = i >> 2, part = i & 3;
                uint4 t = *reinterpret_cast<const uint4*>(Bm + (size_t)(bn + row) * ldb + k0 + part * 8);
                *reinterpret_cast<uint4*>(&Bs[row * LDK + part * 8]) = t;
            }
        } else {
#pragma unroll
            for (int i = tid; i < 32 * (BN / 8); i += NT) {
                int kk = i / (BN / 8);
                int ng = (i % (BN / 8)) * 8;
                uint4 t = *reinterpret_cast<const uint4*>(Bm + (size_t)(k0 + kk) * ldb + bn + ng);
                __nv_bfloat16 pv[8];
                memcpy(pv, &t, 16);
#pragma unroll
                for (int j = 0; j < 8; j++) Bs[(ng + j) * LDK + kk] = pv[j];
            }
        }
        __syncthreads();

#pragma unroll
        for (int ks = 0; ks < 2; ks++) {
            int kb = ks * 16 + cg;
            uint32_t af[MFRAG][4], bf[NFRAG][2];
#pragma unroll
            for (int mf = 0; mf < MFRAG; mf++) {
                const __nv_bfloat16* p = &As[(wm + mf * 16 + rg) * LDK + kb];
                af[mf][0] = *reinterpret_cast<const uint32_t*>(p);
                af[mf][1] = *reinterpret_cast<const uint32_t*>(p + 8 * LDK);
                af[mf][2] = *reinterpret_cast<const uint32_t*>(p + 8);
                af[mf][3] = *reinterpret_cast<const uint32_t*>(p + 8 * LDK + 8);
            }
#pragma unroll
            for (int nf = 0; nf < NFRAG; nf++) {
                const __nv_bfloat16* p = &Bs[(wn + nf * 8 + rg) * LDK + kb];
                bf[nf][0] = *reinterpret_cast<const uint32_t*>(p);
                bf[nf][1] = *reinterpret_cast<const uint32_t*>(p + 8);
            }
#pragma unroll
            for (int mf = 0; mf < MFRAG; mf++)
#pragma unroll
                for (int nf = 0; nf < NFRAG; nf++)
                    mma16816(acc[mf][nf], af[mf], bf[nf]);
        }
        __syncthreads();
    }

    // ---- epilogue ----
#pragma unroll
    for (int mf = 0; mf < MFRAG; mf++) {
#pragma unroll
        for (int nf = 0; nf < NFRAG; nf++) {
            int n0 = bn + wn + nf * 8 + cg;
#pragma unroll
            for (int hrow = 0; hrow < 2; hrow++) {
                int m = bm + wm + mf * 16 + rg + hrow * 8;
                float v0 = acc[mf][nf][hrow * 2 + 0];
                float v1 = acc[mf][nf][hrow * 2 + 1];
                if (HAS_BIAS) { v0 += bias[n0]; v1 += bias[n0 + 1]; }
                if (HAS_ADD) {
                    float2 a2 = *reinterpret_cast<const float2*>(
                        addsrc + coff + (size_t)m * ldadd + n0);
                    v0 += a2.x; v1 += a2.y;
                }
                if (OUT_BF16) {
                    __nv_bfloat162 o = __floats2bfloat162_rn(v0, v1);
                    *reinterpret_cast<__nv_bfloat162*>(
                        (__nv_bfloat16*)Cv + coff + (size_t)m * ldc + n0) = o;
                } else {
                    float2 o; o.x = v0; o.y = v1;
                    *reinterpret_cast<float2*>(
                        (float*)Cv + coff + (size_t)m * ldc + n0) = o;
                }
            }
        }
    }
}

// ---------------- launch ----------------
extern "C" void kernel_launch(void* const* d_in, const int* in_sizes, int n_in,
                              void* d_out, int out_size) {
    const float* x    = (const float*)d_in[0];
    const float* xf   = (const float*)d_in[1];
    const float* emb  = (const float*)d_in[2];
    const float* ln_g = (const float*)d_in[3];
    const float* ln_b = (const float*)d_in[4];
    const float* cln_g= (const float*)d_in[5];
    const float* cln_b= (const float*)d_in[6];
    const float* Wq   = (const float*)d_in[7];
    const float* bq   = (const float*)d_in[8];
    const float* Wk   = (const float*)d_in[9];
    const float* bk   = (const float*)d_in[10];
    const float* Wv   = (const float*)d_in[11];
    const float* bv   = (const float*)d_in[12];
    const float* sln_g= (const float*)d_in[13];
    const float* sln_b= (const float*)d_in[14];
    const float* Wemb = (const float*)d_in[15];
    const float* bemb = (const float*)d_in[16];
    const float* Wout = (const float*)d_in[17];
    const float* bout = (const float*)d_in[18];
    float* out = (float*)d_out;

    __nv_bfloat16 *xn, *xfn, *q, *k, *v, *s, *hbf, *wqt, *wkt, *wvt, *woutt;
    float *y, *semb, *embo, *embp;
    cudaGetSymbolAddress((void**)&xn,   g_xn_bf);
    cudaGetSymbolAddress((void**)&xfn,  g_xfn_bf);
    cudaGetSymbolAddress((void**)&q,    g_q_bf);
    cudaGetSymbolAddress((void**)&k,    g_k_bf);
    cudaGetSymbolAddress((void**)&v,    g_v_bf);
    cudaGetSymbolAddress((void**)&s,    g_s_bf);
    cudaGetSymbolAddress((void**)&y,    g_y);
    cudaGetSymbolAddress((void**)&hbf,  g_h_bf);
    cudaGetSymbolAddress((void**)&wqt,  g_wqt);
    cudaGetSymbolAddress((void**)&wkt,  g_wkt);
    cudaGetSymbolAddress((void**)&wvt,  g_wvt);
    cudaGetSymbolAddress((void**)&woutt,g_woutt);
    cudaGetSymbolAddress((void**)&semb, g_semb);
    cudaGetSymbolAddress((void**)&embo, g_embo);
    cudaGetSymbolAddress((void**)&embp, g_embp);

    dim3 tb(32, 8);

    // 1. LayerNorms -> bf16
    ln_bf16_kernel<<<Bsz * Tsz, 256>>>(x,  ln_g,  ln_b,  xn,  Dsz);
    ln_bf16_kernel<<<Bsz * Nsz, 256>>>(xf, cln_g, cln_b, xfn, Lsz);

    // 2. weight convert+transpose  [K][N] fp32 -> [N][K] bf16
    transconv_kernel<<<dim3(Dsz/32, Dsz/32), tb>>>(Wq,   wqt,   Dsz, Dsz);
    transconv_kernel<<<dim3(Dsz/32, Lsz/32), tb>>>(Wk,   wkt,   Lsz, Dsz);
    transconv_kernel<<<dim3(Dsz/32, Lsz/32), tb>>>(Wv,   wvt,   Lsz, Dsz);
    transconv_kernel<<<dim3(Dsz/32, Dsz/32), tb>>>(Wout, woutt, Dsz, Dsz);

    // 3. emb path
    silu_kernel<<<(Bsz * TEsz + 255) / 256, 256>>>(emb, semb, Bsz * TEsz);
    embgemm_part<<<dim3(64, 8), 256>>>(semb, Wemb, embp);
    embgemm_reduce<<<64, 256>>>(embp, bemb, embo);

    // 4. projections (bf16 out)
    mma_gemm<128,128,2,4,true,true,false,true><<<dim3(Dsz/128, (Bsz*Tsz)/128, 1), 256>>>(
        Bsz*Tsz, Dsz, Dsz, xn, Dsz, 0, 0, wqt, Dsz, 0, 0, q, Dsz, 0, 0, bq, nullptr, 0, 1);
    mma_gemm<128,128,2,4,true,true,false,true><<<dim3(Dsz/128, (Bsz*Nsz)/128, 1), 256>>>(
        Bsz*Nsz, Dsz, Lsz, xfn, Lsz, 0, 0, wkt, Lsz, 0, 0, k, Dsz, 0, 0, bk, nullptr, 0, 1);
    mma_gemm<128,128,2,4,true,true,false,true><<<dim3(Dsz/128, (Bsz*Nsz)/128, 1), 256>>>(
        Bsz*Nsz, Dsz, Lsz, xfn, Lsz, 0, 0, wvt, Lsz, 0, 0, v, Dsz, 0, 0, bv, nullptr, 0, 1);

    // 5. scores: per (b,h) S(T,N) = q @ k^T  (bf16 out, layout (b,h,t,n))
    {
        long long sAb = (long long)Tsz * Dsz, sAh = HDsz;
        long long sBb = (long long)Nsz * Dsz, sBh = HDsz;
        long long sCb = (long long)Hsz * Tsz * Nsz, sCh = (long long)Tsz * Nsz;
        mma_gemm<128,128,2,4,true,false,false,true><<<dim3(Nsz/128, Tsz/128, Bsz*Hsz), 256>>>(
            Tsz, Nsz, HDsz, q, Dsz, sAb, sAh, k, Dsz, sBb, sBh,
            s, Nsz, sCb, sCh, nullptr, nullptr, 0, Hsz);
    }

    // 6. softmax over N (1/8 folded), bf16 in-place
    softmax_kernel<<<(Bsz * Hsz * Tsz) / 8, 256>>>(s);

    // 7. y: per (b,h) y(T,hd) = S @ v, written into (B,T,D) fp32
    {
        long long sAb = (long long)Hsz * Tsz * Nsz, sAh = (long long)Tsz * Nsz;
        long long sBb = (long long)Nsz * Dsz, sBh = HDsz;
        long long sCb = (long long)Tsz * Dsz, sCh = HDsz;
        mma_gemm<128,64,2,4,false,false,false,false><<<dim3(HDsz/64, Tsz/128, Bsz*Hsz), 256>>>(
            Tsz, HDsz, Nsz, s, Nsz, sAb, sAh, v, Dsz, sBb, sBh,
            y, Dsz, sCb, sCh, nullptr, nullptr, 0, Hsz);
    }

    // 8. stylization front: hbf = silu(LN(y)*(1+scale)+shift) in bf16
    styl_kernel<<<Bsz * Tsz, 256>>>(y, sln_g, sln_b, embo, hbf);

    // 9. out = x + hbf @ Wout + bout  (fp32 out)
    mma_gemm<128,128,2,4,true,true,true,false><<<dim3(Dsz/128, (Bsz*Tsz)/128, 1), 256>>>(
        Bsz*Tsz, Dsz, Dsz, hbf, Dsz, 0, 0, woutt, Dsz, 0, 0,
        out, Dsz, 0, 0, bout, x, Dsz, 1);
}

// round 11
// speedup vs baseline: 4.2560x; 1.1890x over previous
#include <cuda_runtime.h>
#include <cuda_bf16.h>
#include <math.h>
#include <stdint.h>
#include <string.h>

// ---------------- problem constants ----------------
#define Bsz   8
#define Tsz   1024
#define Dsz   1024
#define Nsz   256
#define Lsz   768
#define Hsz   16
#define HDsz  64
#define TEsz  2048
#define D2sz  2048
#define EPSv  1e-5f

// ---------------- scratch (device globals; allocation-free) ----------------
__device__ __align__(256) __nv_bfloat16 g_xn_bf [Bsz * Tsz * Dsz];
__device__ __align__(256) __nv_bfloat16 g_xfn_bf[Bsz * Nsz * Lsz];
__device__ __align__(256) __nv_bfloat16 g_q_bf  [Bsz * Tsz * Dsz];
__device__ __align__(256) __nv_bfloat16 g_k_bf  [Bsz * Nsz * Dsz];
__device__ __align__(256) __nv_bfloat16 g_v_bf  [Bsz * Nsz * Dsz];
__device__ __align__(256) __nv_bfloat16 g_vt_bf [Bsz * Dsz * Nsz];             // v^T per batch: [b][d][n]
__device__ __align__(256) __nv_bfloat16 g_s_bf  [(size_t)Bsz * Hsz * Tsz * Nsz]; // softmaxed probs (b,h,t,n)
__device__ __align__(256) float         g_y     [Bsz * Tsz * Dsz];
__device__ __align__(256) __nv_bfloat16 g_h_bf  [Bsz * Tsz * Dsz];
__device__ __align__(256) __nv_bfloat16 g_wqt   [Dsz * Dsz];
__device__ __align__(256) __nv_bfloat16 g_wkt   [Dsz * Lsz];
__device__ __align__(256) __nv_bfloat16 g_wvt   [Dsz * Lsz];
__device__ __align__(256) __nv_bfloat16 g_woutt [Dsz * Dsz];
__device__ __align__(256) float         g_embo  [Bsz * D2sz];
__device__ __align__(256) float         g_embp  [8 * Bsz * D2sz];

// ---------------- helpers ----------------
__device__ __forceinline__ uint32_t smem_u32(const void* p) {
    uint32_t a;
    asm("{ .reg .u64 t; cvta.to.shared.u64 t, %1; cvt.u32.u64 %0, t; }" : "=r"(a) : "l"(p));
    return a;
}
#define CPA16(dst, src) \
    asm volatile("cp.async.cg.shared.global [%0], [%1], 16;" :: "r"(dst), "l"(src))
#define CPCOMMIT() asm volatile("cp.async.commit_group;")
#define CPWAIT1()  asm volatile("cp.async.wait_group 1;")
#define CPWAIT0()  asm volatile("cp.async.wait_group 0;")

__device__ __forceinline__ void mma16816(float* c, const uint32_t* a, const uint32_t* b) {
    asm volatile(
        "mma.sync.aligned.m16n8k16.row.col.f32.bf16.bf16.f32 "
        "{%0,%1,%2,%3}, {%4,%5,%6,%7}, {%8,%9}, {%0,%1,%2,%3};\n"
        : "+f"(c[0]), "+f"(c[1]), "+f"(c[2]), "+f"(c[3])
        : "r"(a[0]), "r"(a[1]), "r"(a[2]), "r"(a[3]), "r"(b[0]), "r"(b[1]));
}

// ================ cp.async-pipelined bf16 TN GEMM ================
// C[m,n] = sum_k A[m,k] * B[n,k]  (+bias[n]) (+addsrc[m,n]); both operands k-contig.
// BM=128, BK=32 (2-stage cp.async double buffer), 8 warps as 2x4.
template<int BN, bool HAS_BIAS, bool HAS_ADD, bool OUT_BF16>
__global__ void __launch_bounds__(256, 2)
mma_gemm(int K,
         const __nv_bfloat16* __restrict__ A, int lda, long long sAb, long long sAh,
         const __nv_bfloat16* __restrict__ Bm, int ldb, long long sBb, long long sBh,
         void* __restrict__ Cv, int ldc, long long sCb, long long sCh,
         const float* __restrict__ bias,
         const float* __restrict__ addsrc, int ldadd,
         int Hdiv) {
    constexpr int BM = 128, LDK = 40;
    constexpr int WN = BN / 4;
    constexpr int MFRAG = 4;          // WM=64 (2 warp-rows)
    constexpr int NFRAG = WN / 8;

    __shared__ __align__(16) __nv_bfloat16 As[2][BM * LDK];
    __shared__ __align__(16) __nv_bfloat16 Bs[2][BN * LDK];

    int z  = blockIdx.z;
    int zb = z / Hdiv, zh = z % Hdiv;
    A  += (size_t)zb * sAb + (size_t)zh * sAh;
    Bm += (size_t)zb * sBb + (size_t)zh * sBh;
    size_t coff = (size_t)zb * sCb + (size_t)zh * sCh;
    const int bm = blockIdx.y * BM;
    const int bn = blockIdx.x * BN;

    const int tid = threadIdx.x, warp = tid >> 5, lane = tid & 31;
    const int wm = (warp >> 2) * 64;
    const int wn = (warp & 3) * WN;
    const int rg = lane >> 2, cg = (lane & 3) * 2;

    const uint32_t AsA = smem_u32(As), BsA = smem_u32(Bs);

    float acc[MFRAG][NFRAG][4];
#pragma unroll
    for (int i = 0; i < MFRAG; i++)
#pragma unroll
        for (int j = 0; j < NFRAG; j++)
#pragma unroll
            for (int r = 0; r < 4; r++) acc[i][j][r] = 0.f;

    const int KT = K >> 5;

    auto loadt = [&](int kt, int b) {
        const __nv_bfloat16* Ak = A + kt * 32;
#pragma unroll
        for (int i = tid; i < BM * 4; i += 256) {
            int row = i >> 2, part = i & 3;
            CPA16(AsA + (uint32_t)(b * BM * 80 + row * 80 + part * 16),
                  Ak + (size_t)(bm + row) * lda + part * 8);
        }
        const __nv_bfloat16* Bk = Bm + kt * 32;
#pragma unroll
        for (int i = tid; i < BN * 4; i += 256) {
            int row = i >> 2, part = i & 3;
            CPA16(BsA + (uint32_t)(b * BN * 80 + row * 80 + part * 16),
                  Bk + (size_t)(bn + row) * ldb + part * 8);
        }
        CPCOMMIT();
    };

    loadt(0, 0);
    for (int kt = 0; kt < KT; kt++) {
        const int b = kt & 1;
        if (kt + 1 < KT) { loadt(kt + 1, (kt + 1) & 1); CPWAIT1(); }
        else             { CPWAIT0(); }
        __syncthreads();
        const __nv_bfloat16* Ab = As[b];
        const __nv_bfloat16* Bb = Bs[b];
#pragma unroll
        for (int ks = 0; ks < 2; ks++) {
            int kb = ks * 16 + cg;
            uint32_t af[MFRAG][4], bf[NFRAG][2];
#pragma unroll
            for (int mf = 0; mf < MFRAG; mf++) {
                const __nv_bfloat16* p = &Ab[(wm + mf * 16 + rg) * LDK + kb];
                af[mf][0] = *reinterpret_cast<const uint32_t*>(p);
                af[mf][1] = *reinterpret_cast<const uint32_t*>(p + 8 * LDK);
                af[mf][2] = *reinterpret_cast<const uint32_t*>(p + 8);
                af[mf][3] = *reinterpret_cast<const uint32_t*>(p + 8 * LDK + 8);
            }
#pragma unroll
            for (int nf = 0; nf < NFRAG; nf++) {
                const __nv_bfloat16* p = &Bb[(wn + nf * 8 + rg) * LDK + kb];
                bf[nf][0] = *reinterpret_cast<const uint32_t*>(p);
                bf[nf][1] = *reinterpret_cast<const uint32_t*>(p + 8);
            }
#pragma unroll
            for (int mf = 0; mf < MFRAG; mf++)
#pragma unroll
                for (int nf = 0; nf < NFRAG; nf++)
                    mma16816(acc[mf][nf], af[mf], bf[nf]);
        }
        __syncthreads();
    }

    // ---- epilogue ----
#pragma unroll
    for (int mf = 0; mf < MFRAG; mf++) {
#pragma unroll
        for (int nf = 0; nf < NFRAG; nf++) {
            int n0 = bn + wn + nf * 8 + cg;
#pragma unroll
            for (int hrow = 0; hrow < 2; hrow++) {
                int m = bm + wm + mf * 16 + rg + hrow * 8;
                float v0 = acc[mf][nf][hrow * 2 + 0];
                float v1 = acc[mf][nf][hrow * 2 + 1];
                if (HAS_BIAS) { v0 += bias[n0]; v1 += bias[n0 + 1]; }
                if (HAS_ADD) {
                    float2 a2 = *reinterpret_cast<const float2*>(
                        addsrc + coff + (size_t)m * ldadd + n0);
                    v0 += a2.x; v1 += a2.y;
                }
                if (OUT_BF16) {
                    __nv_bfloat162 o = __floats2bfloat162_rn(v0, v1);
                    *reinterpret_cast<__nv_bfloat162*>(
                        (__nv_bfloat16*)Cv + coff + (size_t)m * ldc + n0) = o;
                } else {
                    float2 o; o.x = v0; o.y = v1;
                    *reinterpret_cast<float2*>(
                        (float*)Cv + coff + (size_t)m * ldc + n0) = o;
                }
            }
        }
    }
}

// ================ scores GEMM + fused softmax ================
// Per (b,h): S(128 t-rows, 256 n-cols) = q(128,64) @ k(256,64)^T, scale 1/8,
// softmax over n (full row in-CTA), bf16 probability output to (b,h,t,n).
__global__ void __launch_bounds__(256)
scores_softmax_kernel(const __nv_bfloat16* __restrict__ qp,
                      const __nv_bfloat16* __restrict__ kp,
                      __nv_bfloat16* __restrict__ S) {
    constexpr int LDK = 40;
    __shared__ __align__(16) __nv_bfloat16 As[128 * LDK];
    __shared__ __align__(16) __nv_bfloat16 Bs[256 * LDK];
    __shared__ float sred[2][64][4];

    const int z  = blockIdx.z;            // b*16+h
    const int zb = z >> 4, zh = z & 15;
    const __nv_bfloat16* A = qp + (size_t)zb * Tsz * Dsz + zh * HDsz;
    const __nv_bfloat16* B = kp + (size_t)zb * Nsz * Dsz + zh * HDsz;
    __nv_bfloat16* C = S + (size_t)z * Tsz * Nsz;
    const int bm = blockIdx.y * 128;

    const int tid = threadIdx.x, warp = tid >> 5, lane = tid & 31;
    const int wr = warp >> 2, wc = warp & 3;      // warp row/col blocks
    const int wm = wr * 64, wn = wc * 64;
    const int rg = lane >> 2, cg = (lane & 3) * 2;

    float acc[4][8][4];
#pragma unroll
    for (int i = 0; i < 4; i++)
#pragma unroll
        for (int j = 0; j < 8; j++)
#pragma unroll
            for (int r = 0; r < 4; r++) acc[i][j][r] = 0.f;

    for (int kt = 0; kt < 2; kt++) {
#pragma unroll
        for (int i = tid; i < 128 * 4; i += 256) {
            int row = i >> 2, part = i & 3;
            uint4 t = *reinterpret_cast<const uint4*>(
                A + (size_t)(bm + row) * Dsz + kt * 32 + part * 8);
            *reinterpret_cast<uint4*>(&As[row * LDK + part * 8]) = t;
        }
#pragma unroll
        for (int i = tid; i < 256 * 4; i += 256) {
            int row = i >> 2, part = i & 3;
            uint4 t = *reinterpret_cast<const uint4*>(
                B + (size_t)row * Dsz + kt * 32 + part * 8);
            *reinterpret_cast<uint4*>(&Bs[row * LDK + part * 8]) = t;
        }
        __syncthreads();
#pragma unroll
        for (int ks = 0; ks < 2; ks++) {
            int kb = ks * 16 + cg;
            uint32_t af[4][4], bf[8][2];
#pragma unroll
            for (int mf = 0; mf < 4; mf++) {
                const __nv_bfloat16* p = &As[(wm + mf * 16 + rg) * LDK + kb];
                af[mf][0] = *reinterpret_cast<const uint32_t*>(p);
                af[mf][1] = *reinterpret_cast<const uint32_t*>(p + 8 * LDK);
                af[mf][2] = *reinterpret_cast<const uint32_t*>(p + 8);
                af[mf][3] = *reinterpret_cast<const uint32_t*>(p + 8 * LDK + 8);
            }
#pragma unroll
            for (int nf = 0; nf < 8; nf++) {
                const __nv_bfloat16* p = &Bs[(wn + nf * 8 + rg) * LDK + kb];
                bf[nf][0] = *reinterpret_cast<const uint32_t*>(p);
                bf[nf][1] = *reinterpret_cast<const uint32_t*>(p + 8);
            }
#pragma unroll
            for (int mf = 0; mf < 4; mf++)
#pragma unroll
                for (int nf = 0; nf < 8; nf++)
                    mma16816(acc[mf][nf], af[mf], bf[nf]);
        }
        __syncthreads();
    }

    // ---- fused softmax over n (rows split across 4 warp-cols) ----
#pragma unroll
    for (int mf = 0; mf < 4; mf++)
#pragma unroll
        for (int nf = 0; nf < 8; nf++)
#pragma unroll
            for (int r = 0; r < 4; r++) acc[mf][nf][r] *= 0.125f;

    float rmax[4][2];
#pragma unroll
    for (int mf = 0; mf < 4; mf++)
#pragma unroll
        for (int hrow = 0; hrow < 2; hrow++) {
            float m = -1e30f;
#pragma unroll
            for (int nf = 0; nf < 8; nf++)
                m = fmaxf(m, fmaxf(acc[mf][nf][hrow * 2], acc[mf][nf][hrow * 2 + 1]));
            m = fmaxf(m, __shfl_xor_sync(0xffffffffu, m, 1));
            m = fmaxf(m, __shfl_xor_sync(0xffffffffu, m, 2));
            if ((lane & 3) == 0) sred[wr][mf * 16 + rg + hrow * 8][wc] = m;
        }
    __syncthreads();
#pragma unroll
    for (int mf = 0; mf < 4; mf++)
#pragma unroll
        for (int hrow = 0; hrow < 2; hrow++) {
            int r = mf * 16 + rg + hrow * 8;
            rmax[mf][hrow] = fmaxf(fmaxf(sred[wr][r][0], sred[wr][r][1]),
                                   fmaxf(sred[wr][r][2], sred[wr][r][3]));
        }
    __syncthreads();
    float rsum[4][2];
#pragma unroll
    for (int mf = 0; mf < 4; mf++)
#pragma unroll
        for (int hrow = 0; hrow < 2; hrow++) {
            float s = 0.f;
#pragma unroll
            for (int nf = 0; nf < 8; nf++) {
                float e0 = __expf(acc[mf][nf][hrow * 2]     - rmax[mf][hrow]);
                float e1 = __expf(acc[mf][nf][hrow * 2 + 1] - rmax[mf][hrow]);
                acc[mf][nf][hrow * 2] = e0; acc[mf][nf][hrow * 2 + 1] = e1;
                s += e0 + e1;
            }
            s += __shfl_xor_sync(0xffffffffu, s, 1);
            s += __shfl_xor_sync(0xffffffffu, s, 2);
            if ((lane & 3) == 0) sred[wr][mf * 16 + rg + hrow * 8][wc] = s;
        }
    __syncthreads();
#pragma unroll
    for (int mf = 0; mf < 4; mf++)
#pragma unroll
        for (int hrow = 0; hrow < 2; hrow++) {
            int r = mf * 16 + rg + hrow * 8;
            float tot = sred[wr][r][0] + sred[wr][r][1] + sred[wr][r][2] + sred[wr][r][3];
            rsum[mf][hrow] = 1.f / tot;
        }
    // ---- store bf16 probabilities ----
#pragma unroll
    for (int mf = 0; mf < 4; mf++)
#pragma unroll
        for (int hrow = 0; hrow < 2; hrow++) {
            int m = bm + wm + mf * 16 + rg + hrow * 8;
            __nv_bfloat16* cp = C + (size_t)m * Nsz + wn + cg;
            float inv = rsum[mf][hrow];
#pragma unroll
            for (int nf = 0; nf < 8; nf++) {
                __nv_bfloat162 o = __floats2bfloat162_rn(
                    acc[mf][nf][hrow * 2] * inv, acc[mf][nf][hrow * 2 + 1] * inv);
                *reinterpret_cast<__nv_bfloat162*>(cp + nf * 8) = o;
            }
        }
}

// ---------------- LayerNorm over last dim -> bf16 ----------------
__global__ void ln_bf16_kernel(const float* __restrict__ in,
                               const float* __restrict__ g,
                               const float* __restrict__ b,
                               __nv_bfloat16* __restrict__ out, int C) {
    int row = blockIdx.x;
    const float* ip = in + (size_t)row * C;
    __nv_bfloat16* op = out + (size_t)row * C;
    int tid = threadIdx.x;
    float v[4];
    float s = 0.f, ss = 0.f;
#pragma unroll
    for (int i = 0; i < 4; i++) {
        int c = tid + i * 256;
        float x = (c < C) ? ip[c] : 0.f;
        v[i] = x; s += x; ss += x * x;
    }
    __shared__ float rs[256], rq[256];
    rs[tid] = s; rq[tid] = ss;
    __syncthreads();
    for (int off = 128; off > 0; off >>= 1) {
        if (tid < off) { rs[tid] += rs[tid + off]; rq[tid] += rq[tid + off]; }
        __syncthreads();
    }
    float mean = rs[0] / (float)C;
    float var  = rq[0] / (float)C - mean * mean;
    float inv  = rsqrtf(var + EPSv);
#pragma unroll
    for (int i = 0; i < 4; i++) {
        int c = tid + i * 256;
        if (c < C) op[c] = __float2bfloat16_rn((v[i] - mean) * inv * g[c] + b[c]);
    }
}

// ---------------- LN + modulate + SiLU -> bf16 ----------------
__global__ void styl_kernel(const float* __restrict__ y,
                            const float* __restrict__ g,
                            const float* __restrict__ b,
                            const float* __restrict__ embout,
                            __nv_bfloat16* __restrict__ out) {
    int row = blockIdx.x;
    int batch = row / Tsz;
    const float* ip = y + (size_t)row * Dsz;
    __nv_bfloat16* op = out + (size_t)row * Dsz;
    const float* sc = embout + (size_t)batch * D2sz;
    const float* sh = embout + (size_t)batch * D2sz + Dsz;
    int tid = threadIdx.x;
    float v[4];
    float s = 0.f, ss = 0.f;
#pragma unroll
    for (int i = 0; i < 4; i++) {
        int c = tid + i * 256;
        float x = ip[c];
        v[i] = x; s += x; ss += x * x;
    }
    __shared__ float rs[256], rq[256];
    rs[tid] = s; rq[tid] = ss;
    __syncthreads();
    for (int off = 128; off > 0; off >>= 1) {
        if (tid < off) { rs[tid] += rs[tid + off]; rq[tid] += rq[tid + off]; }
        __syncthreads();
    }
    float mean = rs[0] / (float)Dsz;
    float var  = rq[0] / (float)Dsz - mean * mean;
    float inv  = rsqrtf(var + EPSv);
#pragma unroll
    for (int i = 0; i < 4; i++) {
        int c = tid + i * 256;
        float h = (v[i] - mean) * inv * g[c] + b[c];
        h = h * (1.f + sc[c]) + sh[c];
        op[c] = __float2bfloat16_rn(h / (1.f + expf(-h)));
    }
}

// ---------------- fused weight convert+transpose (all 4 weights, 1 launch) ----------------
// z=0: Wq(1024x1024), z=1: Wout(1024x1024), z=2: Wk(768x1024), z=3: Wv(768x1024)
__global__ void transconv4_kernel(const float* __restrict__ Wq,  __nv_bfloat16* __restrict__ wqt,
                                  const float* __restrict__ Wo,  __nv_bfloat16* __restrict__ wot,
                                  const float* __restrict__ Wk,  __nv_bfloat16* __restrict__ wkt,
                                  const float* __restrict__ Wv,  __nv_bfloat16* __restrict__ wvt) {
    __shared__ float tile[32][33];
    int zid = blockIdx.z;
    const float* in; __nv_bfloat16* out; int R;
    if (zid == 0)      { in = Wq; out = wqt; R = 1024; }
    else if (zid == 1) { in = Wo; out = wot; R = 1024; }
    else if (zid == 2) { in = Wk; out = wkt; R = 768; }
    else               { in = Wv; out = wvt; R = 768; }
    int c0 = blockIdx.x * 32, r0 = blockIdx.y * 32;
    if (r0 >= R) return;
    int tx = threadIdx.x, ty = threadIdx.y;
#pragma unroll
    for (int i = 0; i < 32; i += 8)
        tile[ty + i][tx] = in[(size_t)(r0 + ty + i) * Dsz + c0 + tx];
    __syncthreads();
#pragma unroll
    for (int i = 0; i < 32; i += 8)
        out[(size_t)(c0 + ty + i) * R + r0 + tx] = __float2bfloat16_rn(tile[tx][ty + i]);
}

// ---------------- v transpose: per batch [256 tok][1024 d] bf16 -> [1024 d][256 tok] ----------------
__global__ void vtrans_kernel(const __nv_bfloat16* __restrict__ in,
                              __nv_bfloat16* __restrict__ out) {
    __shared__ __nv_bfloat16 tile[32][33];
    int b = blockIdx.z;
    int d0 = blockIdx.x * 32, t0 = blockIdx.y * 32;
    int tx = threadIdx.x, ty = threadIdx.y;
#pragma unroll
    for (int i = 0; i < 32; i += 8)
        tile[ty + i][tx] = in[((size_t)b * Nsz + t0 + ty + i) * Dsz + d0 + tx];
    __syncthreads();
#pragma unroll
    for (int i = 0; i < 32; i += 8)
        out[((size_t)b * Dsz + d0 + ty + i) * Nsz + t0 + tx] = tile[tx][ty + i];
}

// ---------------- emb GEMM split-K stage 1 (silu fused via smem stage) ----------------
__global__ void embgemm_part(const float* __restrict__ emb,
                             const float* __restrict__ W,
                             float* __restrict__ part) {
    __shared__ float se[8][256];
    int tid = threadIdx.x;
    int kbase = blockIdx.y * 256;
#pragma unroll
    for (int i = tid; i < 8 * 256; i += 256) {
        int r = i >> 8, c = i & 255;
        float e = emb[(size_t)r * TEsz + kbase + c];
        se[r][c] = e / (1.f + expf(-e));
    }
    __syncthreads();
    int lane = tid & 31, ks = tid >> 5;
    int col = blockIdx.x * 32 + lane;
    float acc[8] = {0,0,0,0,0,0,0,0};
#pragma unroll 4
    for (int j = 0; j < 32; j++) {
        int kk = ks * 32 + j;
        float w = W[(size_t)(kbase + kk) * D2sz + col];
#pragma unroll
        for (int r = 0; r < 8; r++) acc[r] = fmaf(se[r][kk], w, acc[r]);
    }
    __shared__ float sp[8][8][32];
#pragma unroll
    for (int r = 0; r < 8; r++) sp[ks][r][lane] = acc[r];
    __syncthreads();
    int r = tid >> 5;
    float s = 0.f;
#pragma unroll
    for (int s2 = 0; s2 < 8; s2++) s += sp[s2][r][lane];
    part[((size_t)blockIdx.y * 8 + r) * D2sz + col] = s;
}

__global__ void embgemm_reduce(const float* __restrict__ part,
                               const float* __restrict__ bias,
                               float* __restrict__ out) {
    int i = blockIdx.x * 256 + threadIdx.x;
    int r = i / D2sz, c = i % D2sz;
    float s = bias[c];
#pragma unroll
    for (int p = 0; p < 8; p++) s += part[((size_t)p * 8 + r) * D2sz + c];
    out[i] = s;
}

// ---------------- launch ----------------
extern "C" void kernel_launch(void* const* d_in, const int* in_sizes, int n_in,
                              void* d_out, int out_size) {
    const float* x    = (const float*)d_in[0];
    const float* xf   = (const float*)d_in[1];
    const float* emb  = (const float*)d_in[2];
    const float* ln_g = (const float*)d_in[3];
    const float* ln_b = (const float*)d_in[4];
    const float* cln_g= (const float*)d_in[5];
    const float* cln_b= (const float*)d_in[6];
    const float* Wq   = (const float*)d_in[7];
    const float* bq   = (const float*)d_in[8];
    const float* Wk   = (const float*)d_in[9];
    const float* bk   = (const float*)d_in[10];
    const float* Wv   = (const float*)d_in[11];
    const float* bv   = (const float*)d_in[12];
    const float* sln_g= (const float*)d_in[13];
    const float* sln_b= (const float*)d_in[14];
    const float* Wemb = (const float*)d_in[15];
    const float* bemb = (const float*)d_in[16];
    const float* Wout = (const float*)d_in[17];
    const float* bout = (const float*)d_in[18];
    float* out = (float*)d_out;

    __nv_bfloat16 *xn, *xfn, *q, *k, *v, *vt, *s, *hbf, *wqt, *wkt, *wvt, *woutt;
    float *y, *embo, *embp;
    cudaGetSymbolAddress((void**)&xn,   g_xn_bf);
    cudaGetSymbolAddress((void**)&xfn,  g_xfn_bf);
    cudaGetSymbolAddress((void**)&q,    g_q_bf);
    cudaGetSymbolAddress((void**)&k,    g_k_bf);
    cudaGetSymbolAddress((void**)&v,    g_v_bf);
    cudaGetSymbolAddress((void**)&vt,   g_vt_bf);
    cudaGetSymbolAddress((void**)&s,    g_s_bf);
    cudaGetSymbolAddress((void**)&y,    g_y);
    cudaGetSymbolAddress((void**)&hbf,  g_h_bf);
    cudaGetSymbolAddress((void**)&wqt,  g_wqt);
    cudaGetSymbolAddress((void**)&wkt,  g_wkt);
    cudaGetSymbolAddress((void**)&wvt,  g_wvt);
    cudaGetSymbolAddress((void**)&woutt,g_woutt);
    cudaGetSymbolAddress((void**)&embo, g_embo);
    cudaGetSymbolAddress((void**)&embp, g_embp);

    dim3 tb(32, 8);

    // 1. LayerNorms -> bf16
    ln_bf16_kernel<<<Bsz * Tsz, 256>>>(x,  ln_g,  ln_b,  xn,  Dsz);
    ln_bf16_kernel<<<Bsz * Nsz, 256>>>(xf, cln_g, cln_b, xfn, Lsz);

    // 2. all weight convert+transposes in one launch
    transconv4_kernel<<<dim3(32, 32, 4), tb>>>(Wq, wqt, Wout, woutt, Wk, wkt, Wv, wvt);

    // 3. emb path (silu fused into stage 1)
    embgemm_part<<<dim3(64, 8), 256>>>(emb, Wemb, embp);
    embgemm_reduce<<<64, 256>>>(embp, bemb, embo);

    // 4. projections (pipelined mma, bf16 out)
    mma_gemm<128,true,false,true><<<dim3(Dsz/128, (Bsz*Tsz)/128, 1), 256>>>(
        Dsz, xn, Dsz, 0, 0, wqt, Dsz, 0, 0, q, Dsz, 0, 0, bq, nullptr, 0, 1);
    mma_gemm<128,true,false,true><<<dim3(Dsz/128, (Bsz*Nsz)/128, 1), 256>>>(
        Lsz, xfn, Lsz, 0, 0, wkt, Lsz, 0, 0, k, Dsz, 0, 0, bk, nullptr, 0, 1);
    mma_gemm<128,true,false,true><<<dim3(Dsz/128, (Bsz*Nsz)/128, 1), 256>>>(
        Lsz, xfn, Lsz, 0, 0, wvt, Lsz, 0, 0, v, Dsz, 0, 0, bv, nullptr, 0, 1);

    // 4b. v transpose for the y GEMM (TN form)
    vtrans_kernel<<<dim3(Dsz/32, Nsz/32, Bsz), tb>>>(v, vt);

    // 5. scores + fused softmax -> bf16 probabilities (b,h,t,n)
    scores_softmax_kernel<<<dim3(1, Tsz/128, Bsz*Hsz), 256>>>(q, k, s);

    // 6. y: per (b,h) y(T,64) = P(T,256) @ vt_bh(64,256)^T, into (B,T,D) fp32
    {
        long long sAb = (long long)Hsz * Tsz * Nsz, sAh = (long long)Tsz * Nsz;
        long long sBb = (long long)Dsz * Nsz, sBh = (long long)HDsz * Nsz;
        long long sCb = (long long)Tsz * Dsz, sCh = HDsz;
        mma_gemm<64,false,false,false><<<dim3(1, Tsz/128, Bsz*Hsz), 256>>>(
            Nsz, s, Nsz, sAb, sAh, vt, Nsz, sBb, sBh,
            y, Dsz, sCb, sCh, nullptr, nullptr, 0, Hsz);
    }

    // 7. stylization front: hbf = silu(LN(y)*(1+scale)+shift) in bf16
    styl_kernel<<<Bsz * Tsz, 256>>>(y, sln_g, sln_b, embo, hbf);

    // 8. out = x + hbf @ Wout + bout  (fp32 out)
    mma_gemm<128,true,true,false><<<dim3(Dsz/128, (Bsz*Tsz)/128, 1), 256>>>(
        Dsz, hbf, Dsz, 0, 0, woutt, Dsz, 0, 0,
        out, Dsz, 0, 0, bout, x, Dsz, 1);
}

// round 12
// speedup vs baseline: 4.7745x; 1.1218x over previous
#include <cuda_runtime.h>
#include <cuda_bf16.h>
#include <math.h>
#include <stdint.h>
#include <string.h>

// ---------------- problem constants ----------------
#define Bsz   8
#define Tsz   1024
#define Dsz   1024
#define Nsz   256
#define Lsz   768
#define Hsz   16
#define HDsz  64
#define TEsz  2048
#define D2sz  2048
#define EPSv  1e-5f

// ---------------- scratch (device globals; allocation-free) ----------------
__device__ __align__(256) __nv_bfloat16 g_xn_bf [Bsz * Tsz * Dsz];
__device__ __align__(256) __nv_bfloat16 g_xfn_bf[Bsz * Nsz * Lsz];
__device__ __align__(256) __nv_bfloat16 g_q_bf  [Bsz * Tsz * Dsz];
__device__ __align__(256) __nv_bfloat16 g_k_bf  [Bsz * Nsz * Dsz];
__device__ __align__(256) __nv_bfloat16 g_v_bf  [Bsz * Nsz * Dsz];
__device__ __align__(256) float         g_y     [Bsz * Tsz * Dsz];
__device__ __align__(256) __nv_bfloat16 g_h_bf  [Bsz * Tsz * Dsz];
__device__ __align__(256) __nv_bfloat16 g_wqt   [Dsz * Dsz];
__device__ __align__(256) __nv_bfloat16 g_wkt   [Dsz * Lsz];
__device__ __align__(256) __nv_bfloat16 g_wvt   [Dsz * Lsz];
__device__ __align__(256) __nv_bfloat16 g_woutt [Dsz * Dsz];
__device__ __align__(256) float         g_embo  [Bsz * D2sz];
__device__ __align__(256) float         g_embp  [16 * Bsz * D2sz];

// ---------------- helpers ----------------
__device__ __forceinline__ uint32_t smem_u32(const void* p) {
    uint32_t a;
    asm("{ .reg .u64 t; cvta.to.shared.u64 t, %1; cvt.u32.u64 %0, t; }" : "=r"(a) : "l"(p));
    return a;
}
#define CPA16(dst, src) \
    asm volatile("cp.async.cg.shared.global [%0], [%1], 16;" :: "r"(dst), "l"(src))
#define CPCOMMIT() asm volatile("cp.async.commit_group;")
#define CPWAIT1()  asm volatile("cp.async.wait_group 1;")
#define CPWAIT0()  asm volatile("cp.async.wait_group 0;")

__device__ __forceinline__ void mma16816(float* c, const uint32_t* a, const uint32_t* b) {
    asm volatile(
        "mma.sync.aligned.m16n8k16.row.col.f32.bf16.bf16.f32 "
        "{%0,%1,%2,%3}, {%4,%5,%6,%7}, {%8,%9}, {%0,%1,%2,%3};\n"
        : "+f"(c[0]), "+f"(c[1]), "+f"(c[2]), "+f"(c[3])
        : "r"(a[0]), "r"(a[1]), "r"(a[2]), "r"(a[3]), "r"(b[0]), "r"(b[1]));
}

// ================ 3-stage cp.async-pipelined bf16 TN GEMM ================
// C[m,n] = sum_k A[m,k] * B[n,k]  (+bias[n]) (+addsrc[m,n]); operands k-contig.
// BM=128, BK=32, 3-stage ring, 8 warps as 2x4. Dynamic smem: 3*(BM+BN)*80 B.
template<int BN, bool HAS_BIAS, bool HAS_ADD, bool OUT_BF16>
__global__ void __launch_bounds__(256, 2)
mma_gemm3(int K,
          const __nv_bfloat16* __restrict__ A, int lda, long long sAb, long long sAh,
          const __nv_bfloat16* __restrict__ Bm, int ldb, long long sBb, long long sBh,
          void* __restrict__ Cv, int ldc, long long sCb, long long sCh,
          const float* __restrict__ bias,
          const float* __restrict__ addsrc, int ldadd,
          int Hdiv) {
    constexpr int BM = 128, LDK = 40;
    constexpr int WN = BN / 4;
    constexpr int MFRAG = 4;          // WM=64 (2 warp-rows)
    constexpr int NFRAG = WN / 8;
    constexpr int ASTAGE = BM * 80;   // bytes per A stage
    constexpr int BSTAGE = BN * 80;

    extern __shared__ __align__(16) char sm[];
    __nv_bfloat16* AsBase = reinterpret_cast<__nv_bfloat16*>(sm);
    __nv_bfloat16* BsBase = reinterpret_cast<__nv_bfloat16*>(sm + 3 * ASTAGE);

    int z  = blockIdx.z;
    int zb = z / Hdiv, zh = z % Hdiv;
    A  += (size_t)zb * sAb + (size_t)zh * sAh;
    Bm += (size_t)zb * sBb + (size_t)zh * sBh;
    size_t coff = (size_t)zb * sCb + (size_t)zh * sCh;
    const int bm = blockIdx.y * BM;
    const int bn = blockIdx.x * BN;

    const int tid = threadIdx.x, warp = tid >> 5, lane = tid & 31;
    const int wm = (warp >> 2) * 64;
    const int wn = (warp & 3) * WN;
    const int rg = lane >> 2, cg = (lane & 3) * 2;

    const uint32_t AsA = smem_u32(AsBase), BsA = smem_u32(BsBase);

    float acc[MFRAG][NFRAG][4];
#pragma unroll
    for (int i = 0; i < MFRAG; i++)
#pragma unroll
        for (int j = 0; j < NFRAG; j++)
#pragma unroll
            for (int r = 0; r < 4; r++) acc[i][j][r] = 0.f;

    const int KT = K >> 5;

    auto loadt = [&](int kt, int st) {
        const __nv_bfloat16* Ak = A + kt * 32;
#pragma unroll
        for (int i = tid; i < BM * 4; i += 256) {
            int row = i >> 2, part = i & 3;
            CPA16(AsA + (uint32_t)(st * ASTAGE + row * 80 + part * 16),
                  Ak + (size_t)(bm + row) * lda + part * 8);
        }
        const __nv_bfloat16* Bk = Bm + kt * 32;
#pragma unroll
        for (int i = tid; i < BN * 4; i += 256) {
            int row = i >> 2, part = i & 3;
            CPA16(BsA + (uint32_t)(st * BSTAGE + row * 80 + part * 16),
                  Bk + (size_t)(bn + row) * ldb + part * 8);
        }
        CPCOMMIT();
    };

    loadt(0, 0);
    loadt(1, 1);
    int st = 0;
    for (int kt = 0; kt < KT; kt++) {
        if (kt + 1 < KT) CPWAIT1(); else CPWAIT0();
        __syncthreads();
        // safe: buffer (kt+2)%3 == (kt-1)%3 was last read before this barrier
        if (kt + 2 < KT) loadt(kt + 2, (kt + 2) % 3);
        const __nv_bfloat16* Ab = AsBase + st * (ASTAGE / 2);
        const __nv_bfloat16* Bb = BsBase + st * (BSTAGE / 2);
#pragma unroll
        for (int ks = 0; ks < 2; ks++) {
            int kb = ks * 16 + cg;
            uint32_t af[MFRAG][4], bf[NFRAG][2];
#pragma unroll
            for (int mf = 0; mf < MFRAG; mf++) {
                const __nv_bfloat16* p = &Ab[(wm + mf * 16 + rg) * LDK + kb];
                af[mf][0] = *reinterpret_cast<const uint32_t*>(p);
                af[mf][1] = *reinterpret_cast<const uint32_t*>(p + 8 * LDK);
                af[mf][2] = *reinterpret_cast<const uint32_t*>(p + 8);
                af[mf][3] = *reinterpret_cast<const uint32_t*>(p + 8 * LDK + 8);
            }
#pragma unroll
            for (int nf = 0; nf < NFRAG; nf++) {
                const __nv_bfloat16* p = &Bb[(wn + nf * 8 + rg) * LDK + kb];
                bf[nf][0] = *reinterpret_cast<const uint32_t*>(p);
                bf[nf][1] = *reinterpret_cast<const uint32_t*>(p + 8);
            }
#pragma unroll
            for (int mf = 0; mf < MFRAG; mf++)
#pragma unroll
                for (int nf = 0; nf < NFRAG; nf++)
                    mma16816(acc[mf][nf], af[mf], bf[nf]);
        }
        st = (st + 1 == 3) ? 0 : st + 1;
    }

    // ---- epilogue ----
#pragma unroll
    for (int mf = 0; mf < MFRAG; mf++) {
#pragma unroll
        for (int nf = 0; nf < NFRAG; nf++) {
            int n0 = bn + wn + nf * 8 + cg;
#pragma unroll
            for (int hrow = 0; hrow < 2; hrow++) {
                int m = bm + wm + mf * 16 + rg + hrow * 8;
                float v0 = acc[mf][nf][hrow * 2 + 0];
                float v1 = acc[mf][nf][hrow * 2 + 1];
                if (HAS_BIAS) { v0 += bias[n0]; v1 += bias[n0 + 1]; }
                if (HAS_ADD) {
                    float2 a2 = *reinterpret_cast<const float2*>(
                        addsrc + coff + (size_t)m * ldadd + n0);
                    v0 += a2.x; v1 += a2.y;
                }
                if (OUT_BF16) {
                    __nv_bfloat162 o = __floats2bfloat162_rn(v0, v1);
                    *reinterpret_cast<__nv_bfloat162*>(
                        (__nv_bfloat16*)Cv + coff + (size_t)m * ldc + n0) = o;
                } else {
                    float2 o; o.x = v0; o.y = v1;
                    *reinterpret_cast<float2*>(
                        (float*)Cv + coff + (size_t)m * ldc + n0) = o;
                }
            }
        }
    }
}

// ================ fully fused attention: scores + softmax + P@V ================
// Per (b,h, 128-row t-tile): S = q(128,64) @ k(256,64)^T /8; P = softmax_n(S);
// y(128,64) = P @ v(256,64). P lives in smem only (no HBM round trip).
// Dynamic smem layout: [P 128x264 bf16 = 67584B  (phase1: Q at +0, K at +18432)]
//                      [V 256x72 bf16 = 36864B]
#define LDQ 72
#define LDP 264
#define SM_ATT (67584 + 36864)

__global__ void __launch_bounds__(256, 1)
fused_attn_kernel(const __nv_bfloat16* __restrict__ qp,
                  const __nv_bfloat16* __restrict__ kp,
                  const __nv_bfloat16* __restrict__ vp,
                  float* __restrict__ yp) {
    extern __shared__ __align__(16) char sm[];
    __nv_bfloat16* Qs = reinterpret_cast<__nv_bfloat16*>(sm);            // 128 x LDQ
    __nv_bfloat16* Ks = reinterpret_cast<__nv_bfloat16*>(sm + 18432);    // 256 x LDQ
    __nv_bfloat16* Ps = reinterpret_cast<__nv_bfloat16*>(sm);            // 128 x LDP (overwrites Q/K)
    __nv_bfloat16* Vs = reinterpret_cast<__nv_bfloat16*>(sm + 67584);    // 256 x LDQ
    __shared__ float sred[2][64][4];

    const int z  = blockIdx.z;            // b*16 + h
    const int zb = z >> 4, zh = z & 15;
    const __nv_bfloat16* Aq = qp + (size_t)zb * Tsz * Dsz + zh * HDsz;
    const __nv_bfloat16* Bk = kp + (size_t)zb * Nsz * Dsz + zh * HDsz;
    const __nv_bfloat16* Vv = vp + (size_t)zb * Nsz * Dsz + zh * HDsz;
    float* Y = yp + (size_t)zb * Tsz * Dsz + zh * HDsz;
    const int bm = blockIdx.y * 128;

    const int tid = threadIdx.x, warp = tid >> 5, lane = tid & 31;
    const int wr = warp >> 2, wc = warp & 3;
    const int wm = wr * 64, wn = wc * 64;
    const int rg = lane >> 2, cg = (lane & 3) * 2;

    // ---- load Q (128x64), K (256x64), V (256x64) tiles ----
#pragma unroll
    for (int i = tid; i < 128 * 8; i += 256) {
        int row = i >> 3, part = i & 7;
        uint4 t = *reinterpret_cast<const uint4*>(Aq + (size_t)(bm + row) * Dsz + part * 8);
        *reinterpret_cast<uint4*>(&Qs[row * LDQ + part * 8]) = t;
    }
#pragma unroll
    for (int i = tid; i < 256 * 8; i += 256) {
        int row = i >> 3, part = i & 7;
        uint4 t = *reinterpret_cast<const uint4*>(Bk + (size_t)row * Dsz + part * 8);
        *reinterpret_cast<uint4*>(&Ks[row * LDQ + part * 8]) = t;
    }
#pragma unroll
    for (int i = tid; i < 256 * 8; i += 256) {
        int row = i >> 3, part = i & 7;
        uint4 t = *reinterpret_cast<const uint4*>(Vv + (size_t)row * Dsz + part * 8);
        *reinterpret_cast<uint4*>(&Vs[row * LDQ + part * 8]) = t;
    }
    __syncthreads();

    // ---- phase 1: scores S(128,256) = Q @ K^T, warp tile 64x64 ----
    float acc[4][8][4];
#pragma unroll
    for (int i = 0; i < 4; i++)
#pragma unroll
        for (int j = 0; j < 8; j++)
#pragma unroll
            for (int r = 0; r < 4; r++) acc[i][j][r] = 0.f;

#pragma unroll
    for (int ks = 0; ks < 4; ks++) {
        int kb = ks * 16 + cg;
        uint32_t af[4][4], bf[8][2];
#pragma unroll
        for (int mf = 0; mf < 4; mf++) {
            const __nv_bfloat16* p = &Qs[(wm + mf * 16 + rg) * LDQ + kb];
            af[mf][0] = *reinterpret_cast<const uint32_t*>(p);
            af[mf][1] = *reinterpret_cast<const uint32_t*>(p + 8 * LDQ);
            af[mf][2] = *reinterpret_cast<const uint32_t*>(p + 8);
            af[mf][3] = *reinterpret_cast<const uint32_t*>(p + 8 * LDQ + 8);
        }
#pragma unroll
        for (int nf = 0; nf < 8; nf++) {
            const __nv_bfloat16* p = &Ks[(wn + nf * 8 + rg) * LDQ + kb];
            bf[nf][0] = *reinterpret_cast<const uint32_t*>(p);
            bf[nf][1] = *reinterpret_cast<const uint32_t*>(p + 8);
        }
#pragma unroll
        for (int mf = 0; mf < 4; mf++)
#pragma unroll
            for (int nf = 0; nf < 8; nf++)
                mma16816(acc[mf][nf], af[mf], bf[nf]);
    }

    // ---- softmax over n (rows split across 4 warp-cols), scale 1/8 ----
#pragma unroll
    for (int mf = 0; mf < 4; mf++)
#pragma unroll
        for (int nf = 0; nf < 8; nf++)
#pragma unroll
            for (int r = 0; r < 4; r++) acc[mf][nf][r] *= 0.125f;

    float rmax[4][2];
#pragma unroll
    for (int mf = 0; mf < 4; mf++)
#pragma unroll
        for (int hrow = 0; hrow < 2; hrow++) {
            float m = -1e30f;
#pragma unroll
            for (int nf = 0; nf < 8; nf++)
                m = fmaxf(m, fmaxf(acc[mf][nf][hrow * 2], acc[mf][nf][hrow * 2 + 1]));
            m = fmaxf(m, __shfl_xor_sync(0xffffffffu, m, 1));
            m = fmaxf(m, __shfl_xor_sync(0xffffffffu, m, 2));
            if ((lane & 3) == 0) sred[wr][mf * 16 + rg + hrow * 8][wc] = m;
        }
    __syncthreads();
#pragma unroll
    for (int mf = 0; mf < 4; mf++)
#pragma unroll
        for (int hrow = 0; hrow < 2; hrow++) {
            int r = mf * 16 + rg + hrow * 8;
            rmax[mf][hrow] = fmaxf(fmaxf(sred[wr][r][0], sred[wr][r][1]),
                                   fmaxf(sred[wr][r][2], sred[wr][r][3]));
        }
    __syncthreads();
    float rsum[4][2];
#pragma unroll
    for (int mf = 0; mf < 4; mf++)
#pragma unroll
        for (int hrow = 0; hrow < 2; hrow++) {
            float s = 0.f;
#pragma unroll
            for (int nf = 0; nf < 8; nf++) {
                float e0 = __expf(acc[mf][nf][hrow * 2]     - rmax[mf][hrow]);
                float e1 = __expf(acc[mf][nf][hrow * 2 + 1] - rmax[mf][hrow]);
                acc[mf][nf][hrow * 2] = e0; acc[mf][nf][hrow * 2 + 1] = e1;
                s += e0 + e1;
            }
            s += __shfl_xor_sync(0xffffffffu, s, 1);
            s += __shfl_xor_sync(0xffffffffu, s, 2);
            if ((lane & 3) == 0) sred[wr][mf * 16 + rg + hrow * 8][wc] = s;
        }
    __syncthreads();
#pragma unroll
    for (int mf = 0; mf < 4; mf++)
#pragma unroll
        for (int hrow = 0; hrow < 2; hrow++) {
            int r = mf * 16 + rg + hrow * 8;
            float tot = sred[wr][r][0] + sred[wr][r][1] + sred[wr][r][2] + sred[wr][r][3];
            rsum[mf][hrow] = 1.f / tot;
        }
    __syncthreads();   // all Q/K reads done chip-wide before P overwrites them

    // ---- phase 2: store P (bf16) into smem (overwrites Q/K region) ----
#pragma unroll
    for (int mf = 0; mf < 4; mf++)
#pragma unroll
        for (int hrow = 0; hrow < 2; hrow++) {
            int m = wm + mf * 16 + rg + hrow * 8;
            float inv = rsum[mf][hrow];
#pragma unroll
            for (int nf = 0; nf < 8; nf++) {
                __nv_bfloat162 o = __floats2bfloat162_rn(
                    acc[mf][nf][hrow * 2] * inv, acc[mf][nf][hrow * 2 + 1] * inv);
                *reinterpret_cast<__nv_bfloat162*>(&Ps[m * LDP + wn + nf * 8 + cg]) = o;
            }
        }
    __syncthreads();

    // ---- phase 3: y(128,64) = P(128,256) @ V(256,64), warp tile 64x16 ----
    {
        const int wnd = wc * 16;       // output d-columns for this warp
        float acc2[4][2][4];
#pragma unroll
        for (int i = 0; i < 4; i++)
#pragma unroll
            for (int j = 0; j < 2; j++)
#pragma unroll
                for (int r = 0; r < 4; r++) acc2[i][j][r] = 0.f;

#pragma unroll
        for (int ks = 0; ks < 16; ks++) {
            int kb = ks * 16;
            uint32_t af[4][4], bf[2][2];
#pragma unroll
            for (int mf = 0; mf < 4; mf++) {
                const __nv_bfloat16* p = &Ps[(wm + mf * 16 + rg) * LDP + kb + cg];
                af[mf][0] = *reinterpret_cast<const uint32_t*>(p);
                af[mf][1] = *reinterpret_cast<const uint32_t*>(p + 8 * LDP);
                af[mf][2] = *reinterpret_cast<const uint32_t*>(p + 8);
                af[mf][3] = *reinterpret_cast<const uint32_t*>(p + 8 * LDP + 8);
            }
#pragma unroll
            for (int nf = 0; nf < 2; nf++) {
                int dcol = wnd + nf * 8 + rg;
                int kk = kb + cg;
                uint32_t l0 = *reinterpret_cast<const uint16_t*>(&Vs[kk * LDQ + dcol]);
                uint32_t h0 = *reinterpret_cast<const uint16_t*>(&Vs[(kk + 1) * LDQ + dcol]);
                uint32_t l1 = *reinterpret_cast<const uint16_t*>(&Vs[(kk + 8) * LDQ + dcol]);
                uint32_t h1 = *reinterpret_cast<const uint16_t*>(&Vs[(kk + 9) * LDQ + dcol]);
                bf[nf][0] = l0 | (h0 << 16);
                bf[nf][1] = l1 | (h1 << 16);
            }
#pragma unroll
            for (int mf = 0; mf < 4; mf++)
#pragma unroll
                for (int nf = 0; nf < 2; nf++)
                    mma16816(acc2[mf][nf], af[mf], bf[nf]);
        }

        // ---- write y fp32 ----
#pragma unroll
        for (int mf = 0; mf < 4; mf++)
#pragma unroll
            for (int nf = 0; nf < 2; nf++) {
                int d0 = wnd + nf * 8 + cg;
#pragma unroll
                for (int hrow = 0; hrow < 2; hrow++) {
                    int m = bm + wm + mf * 16 + rg + hrow * 8;
                    float2 o;
                    o.x = acc2[mf][nf][hrow * 2 + 0];
                    o.y = acc2[mf][nf][hrow * 2 + 1];
                    *reinterpret_cast<float2*>(&Y[(size_t)m * Dsz + d0]) = o;
                }
            }
    }
}

// ---------------- LayerNorm over last dim -> bf16 ----------------
__global__ void ln_bf16_kernel(const float* __restrict__ in,
                               const float* __restrict__ g,
                               const float* __restrict__ b,
                               __nv_bfloat16* __restrict__ out, int C) {
    int row = blockIdx.x;
    const float* ip = in + (size_t)row * C;
    __nv_bfloat16* op = out + (size_t)row * C;
    int tid = threadIdx.x;
    float v[4];
    float s = 0.f, ss = 0.f;
#pragma unroll
    for (int i = 0; i < 4; i++) {
        int c = tid + i * 256;
        float x = (c < C) ? ip[c] : 0.f;
        v[i] = x; s += x; ss += x * x;
    }
    __shared__ float rs[256], rq[256];
    rs[tid] = s; rq[tid] = ss;
    __syncthreads();
    for (int off = 128; off > 0; off >>= 1) {
        if (tid < off) { rs[tid] += rs[tid + off]; rq[tid] += rq[tid + off]; }
        __syncthreads();
    }
    float mean = rs[0] / (float)C;
    float var  = rq[0] / (float)C - mean * mean;
    float inv  = rsqrtf(var + EPSv);
#pragma unroll
    for (int i = 0; i < 4; i++) {
        int c = tid + i * 256;
        if (c < C) op[c] = __float2bfloat16_rn((v[i] - mean) * inv * g[c] + b[c]);
    }
}

// ---------------- LN + modulate + SiLU -> bf16 ----------------
__global__ void styl_kernel(const float* __restrict__ y,
                            const float* __restrict__ g,
                            const float* __restrict__ b,
                            const float* __restrict__ embout,
                            __nv_bfloat16* __restrict__ out) {
    int row = blockIdx.x;
    int batch = row / Tsz;
    const float* ip = y + (size_t)row * Dsz;
    __nv_bfloat16* op = out + (size_t)row * Dsz;
    const float* sc = embout + (size_t)batch * D2sz;
    const float* sh = embout + (size_t)batch * D2sz + Dsz;
    int tid = threadIdx.x;
    float v[4];
    float s = 0.f, ss = 0.f;
#pragma unroll
    for (int i = 0; i < 4; i++) {
        int c = tid + i * 256;
        float x = ip[c];
        v[i] = x; s += x; ss += x * x;
    }
    __shared__ float rs[256], rq[256];
    rs[tid] = s; rq[tid] = ss;
    __syncthreads();
    for (int off = 128; off > 0; off >>= 1) {
        if (tid < off) { rs[tid] += rs[tid + off]; rq[tid] += rq[tid + off]; }
        __syncthreads();
    }
    float mean = rs[0] / (float)Dsz;
    float var  = rq[0] / (float)Dsz - mean * mean;
    float inv  = rsqrtf(var + EPSv);
#pragma unroll
    for (int i = 0; i < 4; i++) {
        int c = tid + i * 256;
        float h = (v[i] - mean) * inv * g[c] + b[c];
        h = h * (1.f + sc[c]) + sh[c];
        op[c] = __float2bfloat16_rn(h / (1.f + expf(-h)));
    }
}

// ---------------- fused weight convert+transpose (all 4 weights, 1 launch) ----------------
__global__ void transconv4_kernel(const float* __restrict__ Wq,  __nv_bfloat16* __restrict__ wqt,
                                  const float* __restrict__ Wo,  __nv_bfloat16* __restrict__ wot,
                                  const float* __restrict__ Wk,  __nv_bfloat16* __restrict__ wkt,
                                  const float* __restrict__ Wv,  __nv_bfloat16* __restrict__ wvt) {
    __shared__ float tile[32][33];
    int zid = blockIdx.z;
    const float* in; __nv_bfloat16* out; int R;
    if (zid == 0)      { in = Wq; out = wqt; R = 1024; }
    else if (zid == 1) { in = Wo; out = wot; R = 1024; }
    else if (zid == 2) { in = Wk; out = wkt; R = 768; }
    else               { in = Wv; out = wvt; R = 768; }
    int c0 = blockIdx.x * 32, r0 = blockIdx.y * 32;
    if (r0 >= R) return;
    int tx = threadIdx.x, ty = threadIdx.y;
#pragma unroll
    for (int i = 0; i < 32; i += 8)
        tile[ty + i][tx] = in[(size_t)(r0 + ty + i) * Dsz + c0 + tx];
    __syncthreads();
#pragma unroll
    for (int i = 0; i < 32; i += 8)
        out[(size_t)(c0 + ty + i) * R + r0 + tx] = __float2bfloat16_rn(tile[tx][ty + i]);
}

// ---------------- emb GEMM split-K (16 splits, silu fused) ----------------
__global__ void embgemm_part(const float* __restrict__ emb,
                             const float* __restrict__ W,
                             float* __restrict__ part) {
    __shared__ float se[8][128];
    int tid = threadIdx.x;
    int kbase = blockIdx.y * 128;
#pragma unroll
    for (int i = tid; i < 8 * 128; i += 256) {
        int r = i >> 7, c = i & 127;
        float e = emb[(size_t)r * TEsz + kbase + c];
        se[r][c] = e / (1.f + expf(-e));
    }
    __syncthreads();
    int lane = tid & 31, ks = tid >> 5;
    int col = blockIdx.x * 32 + lane;
    float acc[8] = {0,0,0,0,0,0,0,0};
#pragma unroll 4
    for (int j = 0; j < 16; j++) {
        int kk = ks * 16 + j;
        float w = W[(size_t)(kbase + kk) * D2sz + col];
#pragma unroll
        for (int r = 0; r < 8; r++) acc[r] = fmaf(se[r][kk], w, acc[r]);
    }
    __shared__ float sp[8][8][32];
#pragma unroll
    for (int r = 0; r < 8; r++) sp[ks][r][lane] = acc[r];
    __syncthreads();
    int r = tid >> 5;
    float s = 0.f;
#pragma unroll
    for (int s2 = 0; s2 < 8; s2++) s += sp[s2][r][lane];
    part[((size_t)blockIdx.y * 8 + r) * D2sz + col] = s;
}

__global__ void embgemm_reduce(const float* __restrict__ part,
                               const float* __restrict__ bias,
                               float* __restrict__ out) {
    int i = blockIdx.x * 256 + threadIdx.x;
    int r = i / D2sz, c = i % D2sz;
    float s = bias[c];
#pragma unroll
    for (int p = 0; p < 16; p++) s += part[((size_t)p * 8 + r) * D2sz + c];
    out[i] = s;
}

// ---------------- launch ----------------
extern "C" void kernel_launch(void* const* d_in, const int* in_sizes, int n_in,
                              void* d_out, int out_size) {
    const float* x    = (const float*)d_in[0];
    const float* xf   = (const float*)d_in[1];
    const float* emb  = (const float*)d_in[2];
    const float* ln_g = (const float*)d_in[3];
    const float* ln_b = (const float*)d_in[4];
    const float* cln_g= (const float*)d_in[5];
    const float* cln_b= (const float*)d_in[6];
    const float* Wq   = (const float*)d_in[7];
    const float* bq   = (const float*)d_in[8];
    const float* Wk   = (const float*)d_in[9];
    const float* bk   = (const float*)d_in[10];
    const float* Wv   = (const float*)d_in[11];
    const float* bv   = (const float*)d_in[12];
    const float* sln_g= (const float*)d_in[13];
    const float* sln_b= (const float*)d_in[14];
    const float* Wemb = (const float*)d_in[15];
    const float* bemb = (const float*)d_in[16];
    const float* Wout = (const float*)d_in[17];
    const float* bout = (const float*)d_in[18];
    float* out = (float*)d_out;

    __nv_bfloat16 *xn, *xfn, *q, *k, *v, *hbf, *wqt, *wkt, *wvt, *woutt;
    float *y, *embo, *embp;
    cudaGetSymbolAddress((void**)&xn,   g_xn_bf);
    cudaGetSymbolAddress((void**)&xfn,  g_xfn_bf);
    cudaGetSymbolAddress((void**)&q,    g_q_bf);
    cudaGetSymbolAddress((void**)&k,    g_k_bf);
    cudaGetSymbolAddress((void**)&v,    g_v_bf);
    cudaGetSymbolAddress((void**)&y,    g_y);
    cudaGetSymbolAddress((void**)&hbf,  g_h_bf);
    cudaGetSymbolAddress((void**)&wqt,  g_wqt);
    cudaGetSymbolAddress((void**)&wkt,  g_wkt);
    cudaGetSymbolAddress((void**)&wvt,  g_wvt);
    cudaGetSymbolAddress((void**)&woutt,g_woutt);
    cudaGetSymbolAddress((void**)&embo, g_embo);
    cudaGetSymbolAddress((void**)&embp, g_embp);

    const int SMG = 3 * (128 + 128) * 80;          // 61440 B for mma_gemm3<128>
    cudaFuncSetAttribute(mma_gemm3<128,true,false,true >, cudaFuncAttributeMaxDynamicSharedMemorySize, SMG);
    cudaFuncSetAttribute(mma_gemm3<128,true,true ,false>, cudaFuncAttributeMaxDynamicSharedMemorySize, SMG);
    cudaFuncSetAttribute(fused_attn_kernel, cudaFuncAttributeMaxDynamicSharedMemorySize, SM_ATT);

    dim3 tb(32, 8);

    // 1. LayerNorms -> bf16
    ln_bf16_kernel<<<Bsz * Tsz, 256>>>(x,  ln_g,  ln_b,  xn,  Dsz);
    ln_bf16_kernel<<<Bsz * Nsz, 256>>>(xf, cln_g, cln_b, xfn, Lsz);

    // 2. all weight convert+transposes in one launch
    transconv4_kernel<<<dim3(32, 32, 4), tb>>>(Wq, wqt, Wout, woutt, Wk, wkt, Wv, wvt);

    // 3. emb path (silu fused, 16-way split-K)
    embgemm_part<<<dim3(64, 16), 256>>>(emb, Wemb, embp);
    embgemm_reduce<<<64, 256>>>(embp, bemb, embo);

    // 4. projections (3-stage pipelined mma, bf16 out)
    mma_gemm3<128,true,false,true><<<dim3(Dsz/128, (Bsz*Tsz)/128, 1), 256, SMG>>>(
        Dsz, xn, Dsz, 0, 0, wqt, Dsz, 0, 0, q, Dsz, 0, 0, bq, nullptr, 0, 1);
    mma_gemm3<128,true,false,true><<<dim3(Dsz/128, (Bsz*Nsz)/128, 1), 256, SMG>>>(
        Lsz, xfn, Lsz, 0, 0, wkt, Lsz, 0, 0, k, Dsz, 0, 0, bk, nullptr, 0, 1);
    mma_gemm3<128,true,false,true><<<dim3(Dsz/128, (Bsz*Nsz)/128, 1), 256, SMG>>>(
        Lsz, xfn, Lsz, 0, 0, wvt, Lsz, 0, 0, v, Dsz, 0, 0, bv, nullptr, 0, 1);

    // 5. fused attention: scores + softmax + P@V, y fp32 out
    fused_attn_kernel<<<dim3(1, Tsz/128, Bsz*Hsz), 256, SM_ATT>>>(q, k, v, y);

    // 6. stylization front: hbf = silu(LN(y)*(1+scale)+shift) in bf16
    styl_kernel<<<Bsz * Tsz, 256>>>(y, sln_g, sln_b, embo, hbf);

    // 7. out = x + hbf @ Wout + bout  (fp32 out)
    mma_gemm3<128,true,true,false><<<dim3(Dsz/128, (Bsz*Tsz)/128, 1), 256, SMG>>>(
        Dsz, hbf, Dsz, 0, 0, woutt, Dsz, 0, 0,
        out, Dsz, 0, 0, bout, x, Dsz, 1);
}